// round 14
// baseline (speedup 1.0000x reference)
#include <cuda_runtime.h>
#include <cuda_fp16.h>
#include <math.h>
#include <stdint.h>

#define NB 8   // batch

// ---------------- scratch (device globals; no allocation allowed) ----------------
__device__ float g_pyr_ref[3669120];
__device__ float g_pyr_supp[3669120];
__device__ float g_bufA[58720256];   // also used as fp16-split activation bytes
__device__ float g_bufB[58720256];
__device__ float g_flow[1835008];
__device__ float g_flowup[1835008];
__device__ uint4 g_bw[257152];   // fused hi/lo fp16 weight fragments, levels 2-5 (~4.1MB)
__device__ uint2 g_bw1[25088];   // conv1 k8 fragments, levels 2-5 (~200KB)

typedef unsigned long long u64;

// ---------------- packed f32x2 helpers (FFMA path, levels 0-1) ----------------
__device__ __forceinline__ u64 pack2(float lo, float hi) {
    u64 d; asm("mov.b64 %0, {%1, %2};" : "=l"(d) : "f"(lo), "f"(hi)); return d;
}
__device__ __forceinline__ u64 dup2(float v) {
    u64 d; asm("mov.b64 %0, {%1, %1};" : "=l"(d) : "f"(v)); return d;
}
__device__ __forceinline__ void unpack2(u64 v, float& lo, float& hi) {
    asm("mov.b64 {%0, %1}, %2;" : "=f"(lo), "=f"(hi) : "l"(v));
}
__device__ __forceinline__ void fma2(u64& d, u64 a, u64 b) {
    asm("fma.rn.f32x2 %0, %1, %2, %0;" : "+l"(d) : "l"(a), "l"(b));
}

// ---------------- mma helpers ----------------
__device__ __forceinline__ uint32_t smem_u32(const void* p) {
    uint32_t a;
    asm("{ .reg .u64 t; cvta.to.shared.u64 t, %1; cvt.u32.u64 %0, t; }" : "=r"(a) : "l"(p));
    return a;
}
__device__ __forceinline__ void ldmA(uint32_t* a, uint32_t addr) {
    asm volatile("ldmatrix.sync.aligned.m8n8.x4.shared.b16 {%0,%1,%2,%3}, [%4];"
                 : "=r"(a[0]), "=r"(a[1]), "=r"(a[2]), "=r"(a[3]) : "r"(addr));
}
__device__ __forceinline__ void ldmA2(uint32_t* a, uint32_t addr) {
    asm volatile("ldmatrix.sync.aligned.m8n8.x2.shared.b16 {%0,%1}, [%2];"
                 : "=r"(a[0]), "=r"(a[1]) : "r"(addr));
}
__device__ __forceinline__ void mma16816(float* c, const uint32_t* a, uint32_t b0, uint32_t b1) {
    asm volatile("mma.sync.aligned.m16n8k16.row.col.f32.f16.f16.f32 "
                 "{%0,%1,%2,%3}, {%4,%5,%6,%7}, {%8,%9}, {%0,%1,%2,%3};"
                 : "+f"(c[0]), "+f"(c[1]), "+f"(c[2]), "+f"(c[3])
                 : "r"(a[0]), "r"(a[1]), "r"(a[2]), "r"(a[3]), "r"(b0), "r"(b1));
}
__device__ __forceinline__ void mma1688(float* c, const uint32_t* a, uint32_t b0) {
    asm volatile("mma.sync.aligned.m16n8k8.row.col.f32.f16.f16.f32 "
                 "{%0,%1,%2,%3}, {%4,%5}, {%6}, {%0,%1,%2,%3};"
                 : "+f"(c[0]), "+f"(c[1]), "+f"(c[2]), "+f"(c[3])
                 : "r"(a[0]), "r"(a[1]), "r"(b0));
}
__device__ __forceinline__ uint32_t pack_h2(__half a, __half b) {
    __half2 h = __halves2half2(a, b);
    return *(uint32_t*)&h;
}
__device__ __forceinline__ void split16(float v, __half& h, __half& l) {
    h = __float2half_rn(v);
    l = __float2half_rn(v - __half2float(h));
}
// 16B async copy; sz = 16 (copy) or 0 (zero-fill)
__device__ __forceinline__ void cpasync16(uint32_t dst, const uint4* src, int sz) {
    asm volatile("cp.async.ca.shared.global [%0], [%1], 16, %2;"
                 :: "r"(dst), "l"(src), "r"(sz) : "memory");
}
#define CP_COMMIT() asm volatile("cp.async.commit_group;" ::: "memory")
#define CP_WAIT(n)  asm volatile("cp.async.wait_group %0;" :: "n"(n) : "memory")

// ---------------- small elementwise kernels ----------------
__global__ void k_normalize(const float* __restrict__ ref, const float* __restrict__ supp,
                            float* __restrict__ oref, float* __restrict__ osupp,
                            int total, int HW) {
    int i = blockIdx.x * blockDim.x + threadIdx.x;
    if (i >= total) return;
    int c = (i / HW) % 3;
    const float mean[3] = {0.485f, 0.456f, 0.406f};
    const float stdv[3] = {0.229f, 0.224f, 0.225f};
    oref[i]  = (ref[i]  - mean[c]) / stdv[c];
    osupp[i] = (supp[i] - mean[c]) / stdv[c];
}

__global__ void k_avgpool(const float* __restrict__ in, float* __restrict__ out,
                          int total, int H, int W) {
    int i = blockIdx.x * blockDim.x + threadIdx.x;
    if (i >= total) return;
    int x = i % W;
    int y = (i / W) % H;
    int nc = i / (W * H);
    const float* p = in + (size_t)nc * (4 * H * W) + (size_t)(2 * y) * (2 * W) + 2 * x;
    out[i] = 0.25f * (p[0] + p[1] + p[2 * W] + p[2 * W + 1]);
}

// fused: flow upsample + warp + concat; out = fp32 NCHW (out16=0) or compact fp16-split
// 32B/pixel blocks {hi 16B, lo 16B} (out16=1, consumed by conv1-k8)
__global__ void k_prepare2(const float* __restrict__ r, const float* __restrict__ s,
                           const float* __restrict__ flowc, float* __restrict__ fup,
                           void* __restrict__ outv, int H, int W, int lvl0, int out16) {
    int HW = H * W;
    int total = NB * HW;
    int i = blockIdx.x * blockDim.x + threadIdx.x;
    if (i >= total) return;
    int x = i % W;
    int y = (i / W) % H;
    int n = i / HW;
    int pix = y * W + x;

    float f0, f1;
    if (lvl0) {
        f0 = 0.f; f1 = 0.f;
    } else {
        int h = H / 2, w = W / 2;
        float ys = (float)(h - 1) * (float)y / (float)(H - 1);
        float xsf = (float)(w - 1) * (float)x / (float)(W - 1);
        int yy0 = (int)floorf(ys), xx0 = (int)floorf(xsf);
        float wyv = ys - (float)yy0, wxv = xsf - (float)xx0;
        int yy1 = min(yy0 + 1, h - 1), xx1 = min(xx0 + 1, w - 1);
        const float* p0 = flowc + (size_t)(n * 2 + 0) * h * w;
        const float* p1 = p0 + (size_t)h * w;
        {
            float a = p0[yy0 * w + xx0] * (1.f - wyv) + p0[yy1 * w + xx0] * wyv;
            float b = p0[yy0 * w + xx1] * (1.f - wyv) + p0[yy1 * w + xx1] * wyv;
            f0 = 2.0f * (a * (1.f - wxv) + b * wxv);
        }
        {
            float a = p1[yy0 * w + xx0] * (1.f - wyv) + p1[yy1 * w + xx0] * wyv;
            float b = p1[yy0 * w + xx1] * (1.f - wyv) + p1[yy1 * w + xx1] * wyv;
            f1 = 2.0f * (a * (1.f - wxv) + b * wxv);
        }
    }
    fup[((size_t)n * 2 + 0) * HW + pix] = f0;
    fup[((size_t)n * 2 + 1) * HW + pix] = f1;

    float fx = fminf(fmaxf((float)x + f0, 0.f), (float)(W - 1));
    float fy = fminf(fmaxf((float)y + f1, 0.f), (float)(H - 1));
    int x0 = (int)floorf(fx), y0 = (int)floorf(fy);
    int x1 = min(x0 + 1, W - 1), y1 = min(y0 + 1, H - 1);
    float wx = fx - (float)x0, wy = fy - (float)y0;

    float v[8];
#pragma unroll
    for (int c = 0; c < 3; c++) {
        v[c] = r[((size_t)n * 3 + c) * HW + pix];
        const float* sp = s + ((size_t)n * 3 + c) * HW;
        v[3 + c] = sp[y0 * W + x0] * (1.f - wy) * (1.f - wx)
                 + sp[y0 * W + x1] * (1.f - wy) * wx
                 + sp[y1 * W + x0] * wy * (1.f - wx)
                 + sp[y1 * W + x1] * wy * wx;
    }
    v[6] = f0; v[7] = f1;

    if (!out16) {
        float* o = (float*)outv + (size_t)n * 8 * HW + pix;
#pragma unroll
        for (int c = 0; c < 8; c++) o[(size_t)c * HW] = v[c];
    } else {
        uint32_t hw[4], lw[4];
#pragma unroll
        for (int j = 0; j < 4; j++) {
            __half h0, l0, h1, l1;
            split16(v[2 * j], h0, l0);
            split16(v[2 * j + 1], h1, l1);
            hw[j] = pack_h2(h0, h1);
            lw[j] = pack_h2(l0, l1);
        }
        uint4* o = (uint4*)outv + (((size_t)n * H + y) * W + x) * 2;
        o[0] = make_uint4(hw[0], hw[1], hw[2], hw[3]);
        o[1] = make_uint4(lw[0], lw[1], lw[2], lw[3]);
    }
}

// ---------------- weight prep (levels 2-5, convs 2-5 k16 path) ----------------
__global__ void k_wprep_all(const float* __restrict__ w1, const float* __restrict__ w2,
                            const float* __restrict__ w3, const float* __restrict__ w4,
                            const float* __restrict__ w5, uint4* __restrict__ dst) {
    const int LT = 64288;
    int idx = blockIdx.x * blockDim.x + threadIdx.x;
    if (idx >= 4 * LT) return;
    int li = idx / LT;   // 0..3 -> levels 2..5
    int rem = idx % LT;
    const int tot[5]   = {6272, 25088, 25088, 6272, 1568};
    const int cins[5]  = {8, 32, 64, 32, 16};
    const int couts[5] = {32, 64, 32, 16, 2};
    const int NFs[5]   = {4, 8, 4, 2, 1};
    const float* ws[5] = {w1, w2, w3, w4, w5};
    int ci_ = 0;
    while (ci_ < 4 && rem >= tot[ci_]) { rem -= tot[ci_]; ci_++; }
    if (ci_ == 0) { dst[idx] = make_uint4(0, 0, 0, 0); return; }  // conv1 handled by k8 prep
    int Cin = cins[ci_], Cout = couts[ci_], NF = NFs[ci_];
    const float* w = ws[ci_] + (size_t)(2 + li) * Cout * Cin * 49;

    int lane = rem & 31;
    int i2 = rem >> 5;
    int nf = i2 % NF;   i2 /= NF;
    int tap = i2 % 49;
    int chunk = i2 / 49;
    int n = nf * 8 + (lane >> 2);
    int k0 = chunk * 16 + (lane & 3) * 2;
    float v[4];
#pragma unroll
    for (int j = 0; j < 4; j++) {
        int k = k0 + (j >> 1) * 8 + (j & 1);
        v[j] = (n < Cout && k < Cin) ? w[((size_t)n * Cin + k) * 49 + tap] : 0.f;
    }
    __half hh[4], hl[4];
#pragma unroll
    for (int j = 0; j < 4; j++) {
        __half hi = __float2half_rn(v[j]);
        hh[j] = hi;
        hl[j] = __float2half_rn(v[j] - __half2float(hi));
    }
    dst[idx] = make_uint4(pack_h2(hh[0], hh[1]), pack_h2(hh[2], hh[3]),
                          pack_h2(hl[0], hl[1]), pack_h2(hl[2], hl[3]));
}

// conv1 k8 fragments: [li 4][tap 49][nf 4][lane 32] -> uint2 {b0_hi, b0_lo}
__global__ void k_wprep1(const float* __restrict__ w1, uint2* __restrict__ dst) {
    int idx = blockIdx.x * blockDim.x + threadIdx.x;
    if (idx >= 4 * 49 * 4 * 32) return;
    int lane = idx & 31;
    int i2 = idx >> 5;
    int nf = i2 % 4;   i2 /= 4;
    int tap = i2 % 49;
    int li = i2 / 49;
    const float* w = w1 + (size_t)(2 + li) * 32 * 8 * 49;
    int n = nf * 8 + (lane >> 2);
    int k0 = (lane & 3) * 2;
    float v0 = w[((size_t)n * 8 + k0) * 49 + tap];
    float v1 = w[((size_t)n * 8 + k0 + 1) * 49 + tap];
    __half h0, l0, h1, l1;
    split16(v0, h0, l0);
    split16(v1, h1, l1);
    dst[idx] = make_uint2(pack_h2(h0, h1), pack_h2(l0, l1));
}

// ---------------- conv1: k8 mma (Cin=8, Cout=32), levels 2-5 ----------------
__global__ void __launch_bounds__(256, 2)
k_conv1_mma8(const uint4* __restrict__ in, const uint2* __restrict__ bw,
             const float* __restrict__ bias, uint32_t* __restrict__ ob,
             int H, int W) {
    constexpr int MI = 4, NF = 4;
    constexpr int TX = 64, TW = 70;
    constexpr int PART = 14 * TW * 16;   // 15680 bytes per part
    extern __shared__ char smem[];
    uint32_t A0 = smem_u32(smem);

    int tid = threadIdx.x;
    int wid = tid >> 5;
    int lane = tid & 31;

    int x0 = blockIdx.x * TX;
    if (x0 > W - TX) x0 = W - TX;
    if (x0 < 0) x0 = 0;
    int y0 = blockIdx.y * 8;
    int n  = blockIdx.z;

    float C[MI][NF][4];
#pragma unroll
    for (int mi = 0; mi < MI; mi++)
#pragma unroll
        for (int nf = 0; nf < NF; nf++)
#pragma unroll
            for (int j = 0; j < 4; j++) C[mi][nf][j] = 0.f;

    // async build: 16B hi + 16B lo per pixel
    const uint4* ipc = in + ((size_t)n * H * W) * 2;
    for (int idx = tid; idx < 14 * TW; idx += 256) {
        int r = idx / TW, xt = idx % TW;
        int iy = y0 - 3 + r;
        int ix = x0 - 3 + xt;
        int v = (iy >= 0 && iy < H && ix >= 0 && ix < W);
        const uint4* sp = ipc + (v ? ((size_t)iy * W + ix) * 2 : 0);
        int sz = v ? 16 : 0;
        cpasync16(A0 + (uint32_t)idx * 16, sp, sz);
        cpasync16(A0 + PART + (uint32_t)idx * 16, sp + 1, sz);
    }
    CP_COMMIT();
    CP_WAIT(0);
    __syncthreads();

#pragma unroll 1
    for (int tap = 0; tap < 49; tap++) {
        int dy = tap / 7, dx = tap % 7;
        int pixrow = (wid + dy) * TW + dx + (lane & 15);
        uint32_t ah[MI][2], al[MI][2];
#pragma unroll
        for (int mi = 0; mi < MI; mi++) {
            uint32_t at = A0 + (uint32_t)(pixrow + mi * 16) * 16;
            ldmA2(ah[mi], at);
            ldmA2(al[mi], at + PART);
        }
        const uint2* bt = bw + (size_t)tap * NF * 32;
#pragma unroll
        for (int nf = 0; nf < NF; nf++) {
            uint2 wv = bt[nf * 32 + lane];
#pragma unroll
            for (int mi = 0; mi < MI; mi++) {
                mma1688(C[mi][nf], ah[mi], wv.x);
                mma1688(C[mi][nf], ah[mi], wv.y);
                mma1688(C[mi][nf], al[mi], wv.x);
            }
        }
    }

    int y = y0 + wid;
#pragma unroll
    for (int nf = 0; nf < NF; nf++) {
        int c = nf * 8 + (lane & 3) * 2;
        int ch = c >> 4;
        int wd = (c & 15) >> 1;
        float b0 = bias[c], b1 = bias[c + 1];
        size_t rowbase = (((size_t)(n * 2 + ch) * H + y) * W) * 16;
#pragma unroll
        for (int mi = 0; mi < MI; mi++) {
            int xA = x0 + mi * 16 + (lane >> 2);
            float r0 = fmaxf(C[mi][nf][0] + b0, 0.f);
            float r1 = fmaxf(C[mi][nf][1] + b1, 0.f);
            float r2 = fmaxf(C[mi][nf][2] + b0, 0.f);
            float r3 = fmaxf(C[mi][nf][3] + b1, 0.f);
            __half h0, l0, h1, l1, h2, l2, h3, l3;
            split16(r0, h0, l0); split16(r1, h1, l1);
            split16(r2, h2, l2); split16(r3, h3, l3);
            if (xA < W) {
                size_t pb = rowbase + (size_t)xA * 16;
                ob[pb + wd]     = pack_h2(h0, h1);
                ob[pb + 8 + wd] = pack_h2(l0, l1);
            }
            if (xA + 8 < W) {
                size_t pb2 = rowbase + (size_t)(xA + 8) * 16;
                ob[pb2 + wd]     = pack_h2(h2, h3);
                ob[pb2 + 8 + wd] = pack_h2(l2, l3);
            }
        }
    }
}

// ---------------- mma implicit-GEMM 7x7 conv, k16 path, double-buffered ----------------
template <int NF, int MI>
__global__ void __launch_bounds__(256, 2)
k_conv7_mma(const uint4* __restrict__ in, const uint4* __restrict__ bw,
            const float* __restrict__ bias, void* __restrict__ outv,
            const float* __restrict__ resid,
            int nch, int nchO, int Cout, int H, int W, int relu, int out16) {
    constexpr int TX = MI * 16;
    constexpr int TW = TX + 6;
    constexpr int PART = 14 * TW * 32;
    constexpr int BUF = 2 * PART;
    extern __shared__ char smem[];
    uint32_t A0 = smem_u32(smem);

    int tid = threadIdx.x;
    int wid = tid >> 5;
    int lane = tid & 31;

    int x0 = blockIdx.x * TX;
    if (x0 > W - TX) x0 = W - TX;
    if (x0 < 0) x0 = 0;
    int y0 = blockIdx.y * 8;
    int n  = blockIdx.z;

    float C[MI][NF][4];
#pragma unroll
    for (int mi = 0; mi < MI; mi++)
#pragma unroll
        for (int nf = 0; nf < NF; nf++)
#pragma unroll
            for (int j = 0; j < 4; j++) C[mi][nf][j] = 0.f;

    auto build = [&](int chunk) {
        uint32_t base = A0 + (uint32_t)(chunk & 1) * BUF;
        const uint4* ipc = in + (size_t)(n * nch + chunk) * H * W * 4;
        for (int idx = tid; idx < 14 * TW; idx += 256) {
            int r = idx / TW, xt = idx % TW;
            int iy = y0 - 3 + r;
            int ix = x0 - 3 + xt;
            int v = (iy >= 0 && iy < H && ix >= 0 && ix < W);
            const uint4* sp = ipc + (v ? ((size_t)iy * W + ix) * 4 : 0);
            int sz = v ? 16 : 0;
            int s = (idx >> 2) & 1;
            uint32_t p0 = base + (uint32_t)idx * 32;
            uint32_t p1 = p0 + PART;
            cpasync16(p0 + s * 16, sp, sz);
            cpasync16(p0 + (s ^ 1) * 16, sp + 1, sz);
            cpasync16(p1 + s * 16, sp + 2, sz);
            cpasync16(p1 + (s ^ 1) * 16, sp + 3, sz);
        }
        CP_COMMIT();
    };

    build(0);
    for (int chunk = 0; chunk < nch; chunk++) {
        if (chunk + 1 < nch) {
            build(chunk + 1);
            CP_WAIT(1);
        } else {
            CP_WAIT(0);
        }
        __syncthreads();
        uint32_t Ab = A0 + (uint32_t)(chunk & 1) * BUF;

        const uint4* bwc = bw + (size_t)chunk * 49 * NF * 32;
#pragma unroll 1
        for (int tap = 0; tap < 49; tap++) {
            int dy = tap / 7, dx = tap % 7;
            int pixrow = (wid + dy) * TW + dx + (lane & 15);
            uint32_t hsel = (((uint32_t)lane >> 4) ^ (((uint32_t)pixrow >> 2) & 1)) << 4;
            uint32_t ah[MI][4], al[MI][4];
#pragma unroll
            for (int mi = 0; mi < MI; mi++) {
                uint32_t at = Ab + (uint32_t)(pixrow + mi * 16) * 32 + hsel;
                ldmA(ah[mi], at);
                ldmA(al[mi], at + PART);
            }
            const uint4* bt = bwc + (size_t)tap * NF * 32;
#pragma unroll
            for (int nf = 0; nf < NF; nf++) {
                uint4 wv = bt[nf * 32 + lane];
#pragma unroll
                for (int mi = 0; mi < MI; mi++) {
                    mma16816(C[mi][nf], ah[mi], wv.x, wv.y);
                    mma16816(C[mi][nf], ah[mi], wv.z, wv.w);
                    mma16816(C[mi][nf], al[mi], wv.x, wv.y);
                }
            }
        }
        __syncthreads();   // protect buffer reuse two chunks ahead
    }

    int y = y0 + wid;
    if (out16) {
        uint32_t* ob = (uint32_t*)outv;
#pragma unroll
        for (int nf = 0; nf < NF; nf++) {
            int c = nf * 8 + (lane & 3) * 2;
            int ch = c >> 4;
            int wd = (c & 15) >> 1;
            float b0 = bias[c], b1 = bias[c + 1];
            size_t rowbase = (((size_t)(n * nchO + ch) * H + y) * W) * 16;
#pragma unroll
            for (int mi = 0; mi < MI; mi++) {
                int xA = x0 + mi * 16 + (lane >> 2);
                float r0 = C[mi][nf][0] + b0;
                float r1 = C[mi][nf][1] + b1;
                float r2 = C[mi][nf][2] + b0;
                float r3 = C[mi][nf][3] + b1;
                if (relu) {
                    r0 = fmaxf(r0, 0.f); r1 = fmaxf(r1, 0.f);
                    r2 = fmaxf(r2, 0.f); r3 = fmaxf(r3, 0.f);
                }
                __half h0, l0, h1, l1, h2, l2, h3, l3;
                split16(r0, h0, l0); split16(r1, h1, l1);
                split16(r2, h2, l2); split16(r3, h3, l3);
                if (xA < W) {
                    size_t pb = rowbase + (size_t)xA * 16;
                    ob[pb + wd]     = pack_h2(h0, h1);
                    ob[pb + 8 + wd] = pack_h2(l0, l1);
                }
                if (xA + 8 < W) {
                    size_t pb2 = rowbase + (size_t)(xA + 8) * 16;
                    ob[pb2 + wd]     = pack_h2(h2, h3);
                    ob[pb2 + 8 + wd] = pack_h2(l2, l3);
                }
            }
        }
    } else {
        float* out = (float*)outv;
#pragma unroll
        for (int nf = 0; nf < NF; nf++) {
            int c = nf * 8 + (lane & 3) * 2;
            bool v0 = c < Cout, v1 = c + 1 < Cout;
            float b0 = v0 ? bias[c] : 0.f;
            float b1 = v1 ? bias[c + 1] : 0.f;
            size_t off0 = ((size_t)(n * Cout + c) * H + y) * W;
            float* o0 = out + off0;
            float* o1 = o0 + (size_t)H * W;
            const float* rr0 = resid ? resid + off0 : nullptr;
            const float* rr1 = rr0 + (size_t)H * W;
#pragma unroll
            for (int mi = 0; mi < MI; mi++) {
                int xA = x0 + mi * 16 + (lane >> 2);
                float r0 = C[mi][nf][0] + b0;
                float r1 = C[mi][nf][1] + b1;
                float r2 = C[mi][nf][2] + b0;
                float r3 = C[mi][nf][3] + b1;
                if (relu) {
                    r0 = fmaxf(r0, 0.f); r1 = fmaxf(r1, 0.f);
                    r2 = fmaxf(r2, 0.f); r3 = fmaxf(r3, 0.f);
                }
                if (resid) {
                    if (xA < W) {
                        if (v0) r0 += rr0[xA];
                        if (v1) r1 += rr1[xA];
                    }
                    if (xA + 8 < W) {
                        if (v0) r2 += rr0[xA + 8];
                        if (v1) r3 += rr1[xA + 8];
                    }
                }
                if (xA < W) {
                    if (v0) o0[xA] = r0;
                    if (v1) o1[xA] = r1;
                }
                if (xA + 8 < W) {
                    if (v0) o0[xA + 8] = r2;
                    if (v1) o1[xA + 8] = r3;
                }
            }
        }
    }
}

// ---------------- FFMA f32x2 conv (levels 0-1) ----------------
#define CT 8
__global__ __launch_bounds__(256) void k_conv7(
    const float* __restrict__ in, const float* __restrict__ w,
    const float* __restrict__ bias, float* __restrict__ out,
    const float* __restrict__ resid,
    int Cin, int Cout, int H, int W, int relu) {
    __shared__ __align__(16) float s_in[38 * 40];
    __shared__ __align__(16) float s_w[49][CT];

    int coutGroups = (Cout + CT - 1) / CT;
    int cg = blockIdx.z % coutGroups;
    int n  = blockIdx.z / coutGroups;
    int ox0 = blockIdx.x * 32;
    int oy0 = blockIdx.y * 32;
    int tx = threadIdx.x, ty = threadIdx.y;
    int tid = ty * 16 + tx;

    u64 acc[4][CT / 2];
#pragma unroll
    for (int j = 0; j < CT / 2; j++) {
        int c0 = cg * CT + 2 * j, c1 = c0 + 1;
        float b0 = (c0 < Cout) ? bias[c0] : 0.f;
        float b1 = (c1 < Cout) ? bias[c1] : 0.f;
        u64 b = pack2(b0, b1);
        acc[0][j] = b; acc[1][j] = b; acc[2][j] = b; acc[3][j] = b;
    }

    const float2* s_in2 = (const float2*)s_in;

    for (int ci = 0; ci < Cin; ci++) {
        const float* ip = in + (size_t)(n * Cin + ci) * H * W;
        for (int idx = tid; idx < 38 * 38; idx += 256) {
            int ly = idx / 38, lx = idx % 38;
            int iy = oy0 - 3 + ly, ix = ox0 - 3 + lx;
            s_in[ly * 40 + lx] = (iy >= 0 && iy < H && ix >= 0 && ix < W)
                                     ? ip[(size_t)iy * W + ix] : 0.f;
        }
        for (int idx = tid; idx < CT * 49; idx += 256) {
            int co = idx / 49, k = idx % 49;
            int cout = cg * CT + co;
            s_w[k][co] = (cout < Cout) ? w[((size_t)cout * Cin + ci) * 49 + k] : 0.f;
        }
        __syncthreads();

        float ra[8], rb[8];
        {
            int base2 = ((ty * 2) * 40 + tx * 2) >> 1;
#pragma unroll
            for (int j = 0; j < 4; j++) {
                float2 t = s_in2[base2 + j];
                ra[2 * j] = t.x; ra[2 * j + 1] = t.y;
            }
        }
#pragma unroll
        for (int ky = 0; ky < 7; ky++) {
            int base2 = ((ty * 2 + ky + 1) * 40 + tx * 2) >> 1;
#pragma unroll
            for (int j = 0; j < 4; j++) {
                float2 t = s_in2[base2 + j];
                rb[2 * j] = t.x; rb[2 * j + 1] = t.y;
            }
            u64 da = dup2(ra[0]);
            u64 db = dup2(rb[0]);
#pragma unroll
            for (int kx = 0; kx < 7; kx++) {
                u64 da1 = dup2(ra[kx + 1]);
                u64 db1 = dup2(rb[kx + 1]);
                const u64* wp = (const u64*)&s_w[ky * 7 + kx][0];
#pragma unroll
                for (int j = 0; j < CT / 2; j++) {
                    u64 wv = wp[j];
                    fma2(acc[0][j], da,  wv);
                    fma2(acc[1][j], da1, wv);
                    fma2(acc[2][j], db,  wv);
                    fma2(acc[3][j], db1, wv);
                }
                da = da1; db = db1;
            }
#pragma unroll
            for (int j = 0; j < 8; j++) ra[j] = rb[j];
        }
        __syncthreads();
    }

    int oy = oy0 + ty * 2, ox = ox0 + tx * 2;
#pragma unroll
    for (int j = 0; j < CT / 2; j++) {
        int c0 = cg * CT + 2 * j;
#pragma unroll
        for (int p = 0; p < 4; p++) {
            int yy = oy + (p >> 1), xx = ox + (p & 1);
            if (yy < H && xx < W) {
                float v0, v1;
                unpack2(acc[p][j], v0, v1);
                if (relu) { v0 = fmaxf(v0, 0.f); v1 = fmaxf(v1, 0.f); }
                if (c0 < Cout) {
                    size_t o = (size_t)(n * Cout + c0) * H * W + (size_t)yy * W + xx;
                    out[o] = resid ? (v0 + resid[o]) : v0;
                }
                if (c0 + 1 < Cout) {
                    size_t o = (size_t)(n * Cout + c0 + 1) * H * W + (size_t)yy * W + xx;
                    out[o] = resid ? (v1 + resid[o]) : v1;
                }
            }
        }
    }
}

// ---------------- driver ----------------
extern "C" void kernel_launch(void* const* d_in, const int* in_sizes, int n_in,
                              void* d_out, int out_size) {
    const float* ref  = (const float*)d_in[0];
    const float* supp = (const float*)d_in[1];
    const float* Wt[5] = {(const float*)d_in[2], (const float*)d_in[4],
                          (const float*)d_in[6], (const float*)d_in[8],
                          (const float*)d_in[10]};
    const float* Bt[5] = {(const float*)d_in[3], (const float*)d_in[5],
                          (const float*)d_in[7], (const float*)d_in[9],
                          (const float*)d_in[11]};

    float *pr, *ps, *bufA, *bufB, *flow, *fup;
    uint4* bw;
    uint2* bw1;
    cudaGetSymbolAddress((void**)&pr,   g_pyr_ref);
    cudaGetSymbolAddress((void**)&ps,   g_pyr_supp);
    cudaGetSymbolAddress((void**)&bufA, g_bufA);
    cudaGetSymbolAddress((void**)&bufB, g_bufB);
    cudaGetSymbolAddress((void**)&flow, g_flow);
    cudaGetSymbolAddress((void**)&fup,  g_flowup);
    cudaGetSymbolAddress((void**)&bw,   g_bw);
    cudaGetSymbolAddress((void**)&bw1,  g_bw1);

    const int cins[5]   = {8, 32, 64, 32, 16};
    const int couts[5]  = {32, 64, 32, 16, 2};
    const int MIs[5]    = {4, 2, 2, 2, 4};
    const int nchs[5]   = {1, 2, 4, 2, 1};
    const int nchOs[5]  = {2, 4, 2, 1, 0};
    const int prefix[5] = {0, 6272, 31360, 56448, 62720};
    const int LT = 64288;

    // MI=2: PART=17024, double-buffered = 68096; MI=4 (conv5, single chunk) = 62720
    int smemDB = 2 * 2 * 14 * (2 * 16 + 6) * 32;   // 68096
    int smem14 = 2 * 14 * (4 * 16 + 6) * 32;       // 62720 (conv5, nch=1)
    int smemC1 = 2 * 14 * 70 * 16;                 // 31360
    cudaFuncSetAttribute(k_conv7_mma<8, 2>, cudaFuncAttributeMaxDynamicSharedMemorySize, smemDB);
    cudaFuncSetAttribute(k_conv7_mma<4, 2>, cudaFuncAttributeMaxDynamicSharedMemorySize, smemDB);
    cudaFuncSetAttribute(k_conv7_mma<2, 2>, cudaFuncAttributeMaxDynamicSharedMemorySize, smemDB);
    cudaFuncSetAttribute(k_conv7_mma<1, 4>, cudaFuncAttributeMaxDynamicSharedMemorySize, smem14);
    cudaFuncSetAttribute(k_conv1_mma8, cudaFuncAttributeMaxDynamicSharedMemorySize, smemC1);

    // ---- weight prep ----
    {
        int total = 4 * LT;
        k_wprep_all<<<(total + 255) / 256, 256>>>(Wt[0], Wt[1], Wt[2], Wt[3], Wt[4], bw);
        int t1 = 4 * 49 * 4 * 32;
        k_wprep1<<<(t1 + 255) / 256, 256>>>(Wt[0], bw1);
    }

    int off[6];
    {
        int o = 0;
        for (int l = 0; l < 6; l++) {
            off[l] = o;
            o += NB * 3 * (8 << l) * (14 << l);
        }
    }

    {
        int HW = 256 * 448;
        int total = NB * 3 * HW;
        k_normalize<<<(total + 255) / 256, 256>>>(ref, supp, pr + off[5], ps + off[5],
                                                  total, HW);
    }
    for (int l = 5; l >= 1; l--) {
        int H = 8 << (l - 1), W = 14 << (l - 1);
        int total = NB * 3 * H * W;
        int g = (total + 255) / 256;
        k_avgpool<<<g, 256>>>(pr + off[l], pr + off[l - 1], total, H, W);
        k_avgpool<<<g, 256>>>(ps + off[l], ps + off[l - 1], total, H, W);
    }

    for (int l = 0; l < 6; l++) {
        int H = 8 << l, W = 14 << l;
        int HW = H * W;

        int tp = NB * HW;
        k_prepare2<<<(tp + 255) / 256, 256>>>(pr + off[l], ps + off[l], flow, fup,
                                              bufA, H, W, (l == 0) ? 1 : 0,
                                              (l >= 2) ? 1 : 0);

        float* dst = (l == 5) ? (float*)d_out : flow;
        float* io[6] = {bufA, bufB, bufA, bufB, bufA, bufB};
        if (l < 2) {
            dim3 blk(16, 16);
            for (int i = 0; i < 5; i++) {
                int Cin = cins[i], Cout = couts[i];
                dim3 grd((W + 31) / 32, (H + 31) / 32, NB * ((Cout + CT - 1) / CT));
                const float* wp = Wt[i] + (size_t)l * Cout * Cin * 49;
                const float* bp = Bt[i] + (size_t)l * Cout;
                float* o = (i == 4) ? dst : io[i + 1];
                const float* rs = (i == 4) ? fup : nullptr;
                k_conv7<<<grd, blk>>>(io[i], wp, bp, o, rs, Cin, Cout, H, W,
                                      (i < 4) ? 1 : 0);
            }
        } else {
            int li = l - 2;
            for (int i = 0; i < 5; i++) {
                int Cout = couts[i];
                int TX = MIs[i] * 16;
                int nx = (W + TX - 1) / TX;
                dim3 grd(nx, H / 8, NB);
                const float* bp = Bt[i] + (size_t)l * Cout;
                const uint4* inp = (const uint4*)io[i];
                void* o = (i == 4) ? (void*)dst : (void*)io[i + 1];
                const float* rs = (i == 4) ? fup : nullptr;
                int out16 = (i < 4) ? 1 : 0;
                if (i == 0) {
                    const uint2* bw1p = bw1 + (size_t)li * 49 * 4 * 32;
                    k_conv1_mma8<<<grd, 256, smemC1>>>(inp, bw1p, bp,
                                                       (uint32_t*)io[1], H, W);
                } else {
                    const uint4* bwp = bw + (size_t)li * LT + prefix[i];
                    if (i == 1)
                        k_conv7_mma<8, 2><<<grd, 256, smemDB>>>(inp, bwp, bp, o, rs,
                            nchs[i], nchOs[i], Cout, H, W, 1, out16);
                    else if (i == 2)
                        k_conv7_mma<4, 2><<<grd, 256, smemDB>>>(inp, bwp, bp, o, rs,
                            nchs[i], nchOs[i], Cout, H, W, 1, out16);
                    else if (i == 3)
                        k_conv7_mma<2, 2><<<grd, 256, smemDB>>>(inp, bwp, bp, o, rs,
                            nchs[i], nchOs[i], Cout, H, W, 1, out16);
                    else
                        k_conv7_mma<1, 4><<<grd, 256, smem14>>>(inp, bwp, bp, o, rs,
                            nchs[i], nchOs[i], Cout, H, W, 0, out16);
                }
            }
        }
    }
    (void)in_sizes; (void)n_in; (void)out_size;
}

// round 15
// speedup vs baseline: 1.0212x; 1.0212x over previous
#include <cuda_runtime.h>
#include <cuda_fp16.h>
#include <math.h>
#include <stdint.h>

#define NB 8   // batch

// ---------------- scratch (device globals; no allocation allowed) ----------------
__device__ float g_pyr_ref[3669120];
__device__ float g_pyr_supp[3669120];
__device__ float g_bufA[58720256];   // also used as fp16-split activation bytes
__device__ float g_bufB[58720256];
__device__ float g_flow[1835008];
__device__ float g_flowup[1835008];
__device__ uint4 g_bw[257152];   // fused hi/lo fp16 weight fragments, levels 2-5 (~4.1MB)
__device__ uint2 g_bw1[25088];   // conv1 k8 fragments, levels 2-5 (~200KB)

typedef unsigned long long u64;

// ---------------- packed f32x2 helpers (FFMA path, levels 0-1) ----------------
__device__ __forceinline__ u64 pack2(float lo, float hi) {
    u64 d; asm("mov.b64 %0, {%1, %2};" : "=l"(d) : "f"(lo), "f"(hi)); return d;
}
__device__ __forceinline__ u64 dup2(float v) {
    u64 d; asm("mov.b64 %0, {%1, %1};" : "=l"(d) : "f"(v)); return d;
}
__device__ __forceinline__ void unpack2(u64 v, float& lo, float& hi) {
    asm("mov.b64 {%0, %1}, %2;" : "=f"(lo), "=f"(hi) : "l"(v));
}
__device__ __forceinline__ void fma2(u64& d, u64 a, u64 b) {
    asm("fma.rn.f32x2 %0, %1, %2, %0;" : "+l"(d) : "l"(a), "l"(b));
}

// ---------------- mma helpers ----------------
__device__ __forceinline__ uint32_t smem_u32(const void* p) {
    uint32_t a;
    asm("{ .reg .u64 t; cvta.to.shared.u64 t, %1; cvt.u32.u64 %0, t; }" : "=r"(a) : "l"(p));
    return a;
}
__device__ __forceinline__ void ldmA(uint32_t* a, uint32_t addr) {
    asm volatile("ldmatrix.sync.aligned.m8n8.x4.shared.b16 {%0,%1,%2,%3}, [%4];"
                 : "=r"(a[0]), "=r"(a[1]), "=r"(a[2]), "=r"(a[3]) : "r"(addr));
}
__device__ __forceinline__ void ldmA2(uint32_t* a, uint32_t addr) {
    asm volatile("ldmatrix.sync.aligned.m8n8.x2.shared.b16 {%0,%1}, [%2];"
                 : "=r"(a[0]), "=r"(a[1]) : "r"(addr));
}
__device__ __forceinline__ void mma16816(float* c, const uint32_t* a, uint32_t b0, uint32_t b1) {
    asm volatile("mma.sync.aligned.m16n8k16.row.col.f32.f16.f16.f32 "
                 "{%0,%1,%2,%3}, {%4,%5,%6,%7}, {%8,%9}, {%0,%1,%2,%3};"
                 : "+f"(c[0]), "+f"(c[1]), "+f"(c[2]), "+f"(c[3])
                 : "r"(a[0]), "r"(a[1]), "r"(a[2]), "r"(a[3]), "r"(b0), "r"(b1));
}
__device__ __forceinline__ void mma1688(float* c, const uint32_t* a, uint32_t b0) {
    asm volatile("mma.sync.aligned.m16n8k8.row.col.f32.f16.f16.f32 "
                 "{%0,%1,%2,%3}, {%4,%5}, {%6}, {%0,%1,%2,%3};"
                 : "+f"(c[0]), "+f"(c[1]), "+f"(c[2]), "+f"(c[3])
                 : "r"(a[0]), "r"(a[1]), "r"(b0));
}
__device__ __forceinline__ uint32_t pack_h2(__half a, __half b) {
    __half2 h = __halves2half2(a, b);
    return *(uint32_t*)&h;
}
__device__ __forceinline__ void split16(float v, __half& h, __half& l) {
    h = __float2half_rn(v);
    l = __float2half_rn(v - __half2float(h));
}
// 16B async copy; sz = 16 (copy) or 0 (zero-fill)
__device__ __forceinline__ void cpasync16(uint32_t dst, const uint4* src, int sz) {
    asm volatile("cp.async.ca.shared.global [%0], [%1], 16, %2;"
                 :: "r"(dst), "l"(src), "r"(sz) : "memory");
}
#define CP_COMMIT() asm volatile("cp.async.commit_group;" ::: "memory")
#define CP_WAIT0()  asm volatile("cp.async.wait_group 0;" ::: "memory")

// ---------------- small elementwise kernels ----------------
__global__ void k_normalize(const float* __restrict__ ref, const float* __restrict__ supp,
                            float* __restrict__ oref, float* __restrict__ osupp,
                            int total, int HW) {
    int i = blockIdx.x * blockDim.x + threadIdx.x;
    if (i >= total) return;
    int c = (i / HW) % 3;
    const float mean[3] = {0.485f, 0.456f, 0.406f};
    const float stdv[3] = {0.229f, 0.224f, 0.225f};
    oref[i]  = (ref[i]  - mean[c]) / stdv[c];
    osupp[i] = (supp[i] - mean[c]) / stdv[c];
}

__global__ void k_avgpool(const float* __restrict__ in, float* __restrict__ out,
                          int total, int H, int W) {
    int i = blockIdx.x * blockDim.x + threadIdx.x;
    if (i >= total) return;
    int x = i % W;
    int y = (i / W) % H;
    int nc = i / (W * H);
    const float* p = in + (size_t)nc * (4 * H * W) + (size_t)(2 * y) * (2 * W) + 2 * x;
    out[i] = 0.25f * (p[0] + p[1] + p[2 * W] + p[2 * W + 1]);
}

// fused: flow upsample + warp + concat; out = fp32 NCHW (out16=0) or compact fp16-split
// 32B/pixel blocks {hi 16B, lo 16B} (out16=1, consumed by conv1-k8)
__global__ void k_prepare2(const float* __restrict__ r, const float* __restrict__ s,
                           const float* __restrict__ flowc, float* __restrict__ fup,
                           void* __restrict__ outv, int H, int W, int lvl0, int out16) {
    int HW = H * W;
    int total = NB * HW;
    int i = blockIdx.x * blockDim.x + threadIdx.x;
    if (i >= total) return;
    int x = i % W;
    int y = (i / W) % H;
    int n = i / HW;
    int pix = y * W + x;

    float f0, f1;
    if (lvl0) {
        f0 = 0.f; f1 = 0.f;
    } else {
        int h = H / 2, w = W / 2;
        float ys = (float)(h - 1) * (float)y / (float)(H - 1);
        float xsf = (float)(w - 1) * (float)x / (float)(W - 1);
        int yy0 = (int)floorf(ys), xx0 = (int)floorf(xsf);
        float wyv = ys - (float)yy0, wxv = xsf - (float)xx0;
        int yy1 = min(yy0 + 1, h - 1), xx1 = min(xx0 + 1, w - 1);
        const float* p0 = flowc + (size_t)(n * 2 + 0) * h * w;
        const float* p1 = p0 + (size_t)h * w;
        {
            float a = p0[yy0 * w + xx0] * (1.f - wyv) + p0[yy1 * w + xx0] * wyv;
            float b = p0[yy0 * w + xx1] * (1.f - wyv) + p0[yy1 * w + xx1] * wyv;
            f0 = 2.0f * (a * (1.f - wxv) + b * wxv);
        }
        {
            float a = p1[yy0 * w + xx0] * (1.f - wyv) + p1[yy1 * w + xx0] * wyv;
            float b = p1[yy0 * w + xx1] * (1.f - wyv) + p1[yy1 * w + xx1] * wyv;
            f1 = 2.0f * (a * (1.f - wxv) + b * wxv);
        }
    }
    fup[((size_t)n * 2 + 0) * HW + pix] = f0;
    fup[((size_t)n * 2 + 1) * HW + pix] = f1;

    float fx = fminf(fmaxf((float)x + f0, 0.f), (float)(W - 1));
    float fy = fminf(fmaxf((float)y + f1, 0.f), (float)(H - 1));
    int x0 = (int)floorf(fx), y0 = (int)floorf(fy);
    int x1 = min(x0 + 1, W - 1), y1 = min(y0 + 1, H - 1);
    float wx = fx - (float)x0, wy = fy - (float)y0;

    float v[8];
#pragma unroll
    for (int c = 0; c < 3; c++) {
        v[c] = r[((size_t)n * 3 + c) * HW + pix];
        const float* sp = s + ((size_t)n * 3 + c) * HW;
        v[3 + c] = sp[y0 * W + x0] * (1.f - wy) * (1.f - wx)
                 + sp[y0 * W + x1] * (1.f - wy) * wx
                 + sp[y1 * W + x0] * wy * (1.f - wx)
                 + sp[y1 * W + x1] * wy * wx;
    }
    v[6] = f0; v[7] = f1;

    if (!out16) {
        float* o = (float*)outv + (size_t)n * 8 * HW + pix;
#pragma unroll
        for (int c = 0; c < 8; c++) o[(size_t)c * HW] = v[c];
    } else {
        uint32_t hw[4], lw[4];
#pragma unroll
        for (int j = 0; j < 4; j++) {
            __half h0, l0, h1, l1;
            split16(v[2 * j], h0, l0);
            split16(v[2 * j + 1], h1, l1);
            hw[j] = pack_h2(h0, h1);
            lw[j] = pack_h2(l0, l1);
        }
        uint4* o = (uint4*)outv + (((size_t)n * H + y) * W + x) * 2;
        o[0] = make_uint4(hw[0], hw[1], hw[2], hw[3]);
        o[1] = make_uint4(lw[0], lw[1], lw[2], lw[3]);
    }
}

// ---------------- weight prep (levels 2-5, convs 2-5 k16 path) ----------------
__global__ void k_wprep_all(const float* __restrict__ w1, const float* __restrict__ w2,
                            const float* __restrict__ w3, const float* __restrict__ w4,
                            const float* __restrict__ w5, uint4* __restrict__ dst) {
    const int LT = 64288;
    int idx = blockIdx.x * blockDim.x + threadIdx.x;
    if (idx >= 4 * LT) return;
    int li = idx / LT;   // 0..3 -> levels 2..5
    int rem = idx % LT;
    const int tot[5]   = {6272, 25088, 25088, 6272, 1568};
    const int cins[5]  = {8, 32, 64, 32, 16};
    const int couts[5] = {32, 64, 32, 16, 2};
    const int NFs[5]   = {4, 8, 4, 2, 1};
    const float* ws[5] = {w1, w2, w3, w4, w5};
    int ci_ = 0;
    while (ci_ < 4 && rem >= tot[ci_]) { rem -= tot[ci_]; ci_++; }
    if (ci_ == 0) { dst[idx] = make_uint4(0, 0, 0, 0); return; }  // conv1 handled by k8 prep
    int Cin = cins[ci_], Cout = couts[ci_], NF = NFs[ci_];
    const float* w = ws[ci_] + (size_t)(2 + li) * Cout * Cin * 49;

    int lane = rem & 31;
    int i2 = rem >> 5;
    int nf = i2 % NF;   i2 /= NF;
    int tap = i2 % 49;
    int chunk = i2 / 49;
    int n = nf * 8 + (lane >> 2);
    int k0 = chunk * 16 + (lane & 3) * 2;
    float v[4];
#pragma unroll
    for (int j = 0; j < 4; j++) {
        int k = k0 + (j >> 1) * 8 + (j & 1);
        v[j] = (n < Cout && k < Cin) ? w[((size_t)n * Cin + k) * 49 + tap] : 0.f;
    }
    __half hh[4], hl[4];
#pragma unroll
    for (int j = 0; j < 4; j++) {
        __half hi = __float2half_rn(v[j]);
        hh[j] = hi;
        hl[j] = __float2half_rn(v[j] - __half2float(hi));
    }
    dst[idx] = make_uint4(pack_h2(hh[0], hh[1]), pack_h2(hh[2], hh[3]),
                          pack_h2(hl[0], hl[1]), pack_h2(hl[2], hl[3]));
}

// conv1 k8 fragments: [li 4][tap 49][nf 4][lane 32] -> uint2 {b0_hi, b0_lo}
__global__ void k_wprep1(const float* __restrict__ w1, uint2* __restrict__ dst) {
    int idx = blockIdx.x * blockDim.x + threadIdx.x;
    if (idx >= 4 * 49 * 4 * 32) return;
    int lane = idx & 31;
    int i2 = idx >> 5;
    int nf = i2 % 4;   i2 /= 4;
    int tap = i2 % 49;
    int li = i2 / 49;
    const float* w = w1 + (size_t)(2 + li) * 32 * 8 * 49;
    int n = nf * 8 + (lane >> 2);
    int k0 = (lane & 3) * 2;
    float v0 = w[((size_t)n * 8 + k0) * 49 + tap];
    float v1 = w[((size_t)n * 8 + k0 + 1) * 49 + tap];
    __half h0, l0, h1, l1;
    split16(v0, h0, l0);
    split16(v1, h1, l1);
    dst[idx] = make_uint2(pack_h2(h0, h1), pack_h2(l0, l1));
}

// ---------------- conv1: k8 mma (Cin=8, Cout=32), levels 2-5 ----------------
__global__ void __launch_bounds__(256, 2)
k_conv1_mma8(const uint4* __restrict__ in, const uint2* __restrict__ bw,
             const float* __restrict__ bias, uint32_t* __restrict__ ob,
             int H, int W) {
    constexpr int MI = 4, NF = 4;
    constexpr int TX = 64, TW = 70;
    constexpr int PART = 14 * TW * 16;   // 15680 bytes per part
    extern __shared__ char smem[];
    uint32_t A0 = smem_u32(smem);

    int tid = threadIdx.x;
    int wid = tid >> 5;
    int lane = tid & 31;

    int x0 = blockIdx.x * TX;
    if (x0 > W - TX) x0 = W - TX;
    if (x0 < 0) x0 = 0;
    int y0 = blockIdx.y * 8;
    int n  = blockIdx.z;

    float C[MI][NF][4];
#pragma unroll
    for (int mi = 0; mi < MI; mi++)
#pragma unroll
        for (int nf = 0; nf < NF; nf++)
#pragma unroll
            for (int j = 0; j < 4; j++) C[mi][nf][j] = 0.f;

    // async build: 16B hi + 16B lo per pixel
    const uint4* ipc = in + ((size_t)n * H * W) * 2;
    for (int idx = tid; idx < 14 * TW; idx += 256) {
        int r = idx / TW, xt = idx % TW;
        int iy = y0 - 3 + r;
        int ix = x0 - 3 + xt;
        int v = (iy >= 0 && iy < H && ix >= 0 && ix < W);
        const uint4* sp = ipc + (v ? ((size_t)iy * W + ix) * 2 : 0);
        int sz = v ? 16 : 0;
        cpasync16(A0 + (uint32_t)idx * 16, sp, sz);
        cpasync16(A0 + PART + (uint32_t)idx * 16, sp + 1, sz);
    }
    CP_COMMIT();
    CP_WAIT0();
    __syncthreads();

#pragma unroll 1
    for (int tap = 0; tap < 49; tap++) {
        int dy = tap / 7, dx = tap % 7;
        int pixrow = (wid + dy) * TW + dx + (lane & 15);
        uint32_t ah[MI][2], al[MI][2];
#pragma unroll
        for (int mi = 0; mi < MI; mi++) {
            uint32_t at = A0 + (uint32_t)(pixrow + mi * 16) * 16;
            ldmA2(ah[mi], at);
            ldmA2(al[mi], at + PART);
        }
        const uint2* bt = bw + (size_t)tap * NF * 32;
#pragma unroll
        for (int nf = 0; nf < NF; nf++) {
            uint2 wv = bt[nf * 32 + lane];
#pragma unroll
            for (int mi = 0; mi < MI; mi++) {
                mma1688(C[mi][nf], ah[mi], wv.x);
                mma1688(C[mi][nf], ah[mi], wv.y);
                mma1688(C[mi][nf], al[mi], wv.x);
            }
        }
    }

    int y = y0 + wid;
#pragma unroll
    for (int nf = 0; nf < NF; nf++) {
        int c = nf * 8 + (lane & 3) * 2;
        int ch = c >> 4;
        int wd = (c & 15) >> 1;
        float b0 = bias[c], b1 = bias[c + 1];
        size_t rowbase = (((size_t)(n * 2 + ch) * H + y) * W) * 16;
#pragma unroll
        for (int mi = 0; mi < MI; mi++) {
            int xA = x0 + mi * 16 + (lane >> 2);
            float r0 = fmaxf(C[mi][nf][0] + b0, 0.f);
            float r1 = fmaxf(C[mi][nf][1] + b1, 0.f);
            float r2 = fmaxf(C[mi][nf][2] + b0, 0.f);
            float r3 = fmaxf(C[mi][nf][3] + b1, 0.f);
            __half h0, l0, h1, l1, h2, l2, h3, l3;
            split16(r0, h0, l0); split16(r1, h1, l1);
            split16(r2, h2, l2); split16(r3, h3, l3);
            if (xA < W) {
                size_t pb = rowbase + (size_t)xA * 16;
                ob[pb + wd]     = pack_h2(h0, h1);
                ob[pb + 8 + wd] = pack_h2(l0, l1);
            }
            if (xA + 8 < W) {
                size_t pb2 = rowbase + (size_t)(xA + 8) * 16;
                ob[pb2 + wd]     = pack_h2(h2, h3);
                ob[pb2 + 8 + wd] = pack_h2(l2, l3);
            }
        }
    }
}

// ---------------- mma implicit-GEMM 7x7 conv, k16 path (convs 2-5, levels 2-5) ----------------
template <int NF, int MI>
__global__ void __launch_bounds__(256, 2)
k_conv7_mma(const uint4* __restrict__ in, const uint4* __restrict__ bw,
            const float* __restrict__ bias, void* __restrict__ outv,
            const float* __restrict__ resid,
            int nch, int nchO, int Cout, int H, int W, int relu, int out16) {
    constexpr int TX = MI * 16;
    constexpr int TW = TX + 6;
    constexpr int PART = 14 * TW * 32;
    extern __shared__ char smem[];
    uint32_t A0 = smem_u32(smem);

    int tid = threadIdx.x;
    int wid = tid >> 5;
    int lane = tid & 31;

    int x0 = blockIdx.x * TX;
    if (x0 > W - TX) x0 = W - TX;
    if (x0 < 0) x0 = 0;
    int y0 = blockIdx.y * 8;
    int n  = blockIdx.z;

    float C[MI][NF][4];
#pragma unroll
    for (int mi = 0; mi < MI; mi++)
#pragma unroll
        for (int nf = 0; nf < NF; nf++)
#pragma unroll
            for (int j = 0; j < 4; j++) C[mi][nf][j] = 0.f;

    for (int chunk = 0; chunk < nch; chunk++) {
        // ---- async build: 16B copies from pre-split global layout ----
        const uint4* ipc = in + (size_t)(n * nch + chunk) * H * W * 4;
        for (int idx = tid; idx < 14 * TW; idx += 256) {
            int r = idx / TW, xt = idx % TW;
            int iy = y0 - 3 + r;
            int ix = x0 - 3 + xt;
            int v = (iy >= 0 && iy < H && ix >= 0 && ix < W);
            const uint4* sp = ipc + (v ? ((size_t)iy * W + ix) * 4 : 0);
            int sz = v ? 16 : 0;
            int s = (idx >> 2) & 1;
            uint32_t p0 = A0 + (uint32_t)idx * 32;
            uint32_t p1 = p0 + PART;
            cpasync16(p0 + s * 16, sp, sz);
            cpasync16(p0 + (s ^ 1) * 16, sp + 1, sz);
            cpasync16(p1 + s * 16, sp + 2, sz);
            cpasync16(p1 + (s ^ 1) * 16, sp + 3, sz);
        }
        CP_COMMIT();
        CP_WAIT0();
        __syncthreads();

        const uint4* bwc = bw + (size_t)chunk * 49 * NF * 32;

#pragma unroll 1
        for (int tap = 0; tap < 49; tap++) {
            int dy = tap / 7, dx = tap % 7;
            int pixrow = (wid + dy) * TW + dx + (lane & 15);
            uint32_t hsel = (((uint32_t)lane >> 4) ^ (((uint32_t)pixrow >> 2) & 1)) << 4;
            uint32_t ah[MI][4], al[MI][4];
#pragma unroll
            for (int mi = 0; mi < MI; mi++) {
                uint32_t at = A0 + (uint32_t)(pixrow + mi * 16) * 32 + hsel;
                ldmA(ah[mi], at);
                ldmA(al[mi], at + PART);
            }
            const uint4* bt = bwc + (size_t)tap * NF * 32;
#pragma unroll
            for (int nf = 0; nf < NF; nf++) {
                uint4 wv = bt[nf * 32 + lane];
#pragma unroll
                for (int mi = 0; mi < MI; mi++) {
                    mma16816(C[mi][nf], ah[mi], wv.x, wv.y);
                    mma16816(C[mi][nf], ah[mi], wv.z, wv.w);
                    mma16816(C[mi][nf], al[mi], wv.x, wv.y);
                }
            }
        }
        __syncthreads();
    }

    int y = y0 + wid;
    if (out16) {
        uint32_t* ob = (uint32_t*)outv;
#pragma unroll
        for (int nf = 0; nf < NF; nf++) {
            int c = nf * 8 + (lane & 3) * 2;
            int ch = c >> 4;
            int wd = (c & 15) >> 1;
            float b0 = bias[c], b1 = bias[c + 1];
            size_t rowbase = (((size_t)(n * nchO + ch) * H + y) * W) * 16;
#pragma unroll
            for (int mi = 0; mi < MI; mi++) {
                int xA = x0 + mi * 16 + (lane >> 2);
                float r0 = C[mi][nf][0] + b0;
                float r1 = C[mi][nf][1] + b1;
                float r2 = C[mi][nf][2] + b0;
                float r3 = C[mi][nf][3] + b1;
                if (relu) {
                    r0 = fmaxf(r0, 0.f); r1 = fmaxf(r1, 0.f);
                    r2 = fmaxf(r2, 0.f); r3 = fmaxf(r3, 0.f);
                }
                __half h0, l0, h1, l1, h2, l2, h3, l3;
                split16(r0, h0, l0); split16(r1, h1, l1);
                split16(r2, h2, l2); split16(r3, h3, l3);
                if (xA < W) {
                    size_t pb = rowbase + (size_t)xA * 16;
                    ob[pb + wd]     = pack_h2(h0, h1);
                    ob[pb + 8 + wd] = pack_h2(l0, l1);
                }
                if (xA + 8 < W) {
                    size_t pb2 = rowbase + (size_t)(xA + 8) * 16;
                    ob[pb2 + wd]     = pack_h2(h2, h3);
                    ob[pb2 + 8 + wd] = pack_h2(l2, l3);
                }
            }
        }
    } else {
        float* out = (float*)outv;
#pragma unroll
        for (int nf = 0; nf < NF; nf++) {
            int c = nf * 8 + (lane & 3) * 2;
            bool v0 = c < Cout, v1 = c + 1 < Cout;
            float b0 = v0 ? bias[c] : 0.f;
            float b1 = v1 ? bias[c + 1] : 0.f;
            size_t off0 = ((size_t)(n * Cout + c) * H + y) * W;
            float* o0 = out + off0;
            float* o1 = o0 + (size_t)H * W;
            const float* rr0 = resid ? resid + off0 : nullptr;
            const float* rr1 = rr0 + (size_t)H * W;
#pragma unroll
            for (int mi = 0; mi < MI; mi++) {
                int xA = x0 + mi * 16 + (lane >> 2);
                float r0 = C[mi][nf][0] + b0;
                float r1 = C[mi][nf][1] + b1;
                float r2 = C[mi][nf][2] + b0;
                float r3 = C[mi][nf][3] + b1;
                if (relu) {
                    r0 = fmaxf(r0, 0.f); r1 = fmaxf(r1, 0.f);
                    r2 = fmaxf(r2, 0.f); r3 = fmaxf(r3, 0.f);
                }
                if (resid) {
                    if (xA < W) {
                        if (v0) r0 += rr0[xA];
                        if (v1) r1 += rr1[xA];
                    }
                    if (xA + 8 < W) {
                        if (v0) r2 += rr0[xA + 8];
                        if (v1) r3 += rr1[xA + 8];
                    }
                }
                if (xA < W) {
                    if (v0) o0[xA] = r0;
                    if (v1) o1[xA] = r1;
                }
                if (xA + 8 < W) {
                    if (v0) o0[xA + 8] = r2;
                    if (v1) o1[xA + 8] = r3;
                }
            }
        }
    }
}

// ---------------- FFMA f32x2 conv (levels 0-1) ----------------
#define CT 8
__global__ __launch_bounds__(256) void k_conv7(
    const float* __restrict__ in, const float* __restrict__ w,
    const float* __restrict__ bias, float* __restrict__ out,
    const float* __restrict__ resid,
    int Cin, int Cout, int H, int W, int relu) {
    __shared__ __align__(16) float s_in[38 * 40];
    __shared__ __align__(16) float s_w[49][CT];

    int coutGroups = (Cout + CT - 1) / CT;
    int cg = blockIdx.z % coutGroups;
    int n  = blockIdx.z / coutGroups;
    int ox0 = blockIdx.x * 32;
    int oy0 = blockIdx.y * 32;
    int tx = threadIdx.x, ty = threadIdx.y;
    int tid = ty * 16 + tx;

    u64 acc[4][CT / 2];
#pragma unroll
    for (int j = 0; j < CT / 2; j++) {
        int c0 = cg * CT + 2 * j, c1 = c0 + 1;
        float b0 = (c0 < Cout) ? bias[c0] : 0.f;
        float b1 = (c1 < Cout) ? bias[c1] : 0.f;
        u64 b = pack2(b0, b1);
        acc[0][j] = b; acc[1][j] = b; acc[2][j] = b; acc[3][j] = b;
    }

    const float2* s_in2 = (const float2*)s_in;

    for (int ci = 0; ci < Cin; ci++) {
        const float* ip = in + (size_t)(n * Cin + ci) * H * W;
        for (int idx = tid; idx < 38 * 38; idx += 256) {
            int ly = idx / 38, lx = idx % 38;
            int iy = oy0 - 3 + ly, ix = ox0 - 3 + lx;
            s_in[ly * 40 + lx] = (iy >= 0 && iy < H && ix >= 0 && ix < W)
                                     ? ip[(size_t)iy * W + ix] : 0.f;
        }
        for (int idx = tid; idx < CT * 49; idx += 256) {
            int co = idx / 49, k = idx % 49;
            int cout = cg * CT + co;
            s_w[k][co] = (cout < Cout) ? w[((size_t)cout * Cin + ci) * 49 + k] : 0.f;
        }
        __syncthreads();

        float ra[8], rb[8];
        {
            int base2 = ((ty * 2) * 40 + tx * 2) >> 1;
#pragma unroll
            for (int j = 0; j < 4; j++) {
                float2 t = s_in2[base2 + j];
                ra[2 * j] = t.x; ra[2 * j + 1] = t.y;
            }
        }
#pragma unroll
        for (int ky = 0; ky < 7; ky++) {
            int base2 = ((ty * 2 + ky + 1) * 40 + tx * 2) >> 1;
#pragma unroll
            for (int j = 0; j < 4; j++) {
                float2 t = s_in2[base2 + j];
                rb[2 * j] = t.x; rb[2 * j + 1] = t.y;
            }
            u64 da = dup2(ra[0]);
            u64 db = dup2(rb[0]);
#pragma unroll
            for (int kx = 0; kx < 7; kx++) {
                u64 da1 = dup2(ra[kx + 1]);
                u64 db1 = dup2(rb[kx + 1]);
                const u64* wp = (const u64*)&s_w[ky * 7 + kx][0];
#pragma unroll
                for (int j = 0; j < CT / 2; j++) {
                    u64 wv = wp[j];
                    fma2(acc[0][j], da,  wv);
                    fma2(acc[1][j], da1, wv);
                    fma2(acc[2][j], db,  wv);
                    fma2(acc[3][j], db1, wv);
                }
                da = da1; db = db1;
            }
#pragma unroll
            for (int j = 0; j < 8; j++) ra[j] = rb[j];
        }
        __syncthreads();
    }

    int oy = oy0 + ty * 2, ox = ox0 + tx * 2;
#pragma unroll
    for (int j = 0; j < CT / 2; j++) {
        int c0 = cg * CT + 2 * j;
#pragma unroll
        for (int p = 0; p < 4; p++) {
            int yy = oy + (p >> 1), xx = ox + (p & 1);
            if (yy < H && xx < W) {
                float v0, v1;
                unpack2(acc[p][j], v0, v1);
                if (relu) { v0 = fmaxf(v0, 0.f); v1 = fmaxf(v1, 0.f); }
                if (c0 < Cout) {
                    size_t o = (size_t)(n * Cout + c0) * H * W + (size_t)yy * W + xx;
                    out[o] = resid ? (v0 + resid[o]) : v0;
                }
                if (c0 + 1 < Cout) {
                    size_t o = (size_t)(n * Cout + c0 + 1) * H * W + (size_t)yy * W + xx;
                    out[o] = resid ? (v1 + resid[o]) : v1;
                }
            }
        }
    }
}

// ---------------- driver ----------------
extern "C" void kernel_launch(void* const* d_in, const int* in_sizes, int n_in,
                              void* d_out, int out_size) {
    const float* ref  = (const float*)d_in[0];
    const float* supp = (const float*)d_in[1];
    const float* Wt[5] = {(const float*)d_in[2], (const float*)d_in[4],
                          (const float*)d_in[6], (const float*)d_in[8],
                          (const float*)d_in[10]};
    const float* Bt[5] = {(const float*)d_in[3], (const float*)d_in[5],
                          (const float*)d_in[7], (const float*)d_in[9],
                          (const float*)d_in[11]};

    float *pr, *ps, *bufA, *bufB, *flow, *fup;
    uint4* bw;
    uint2* bw1;
    cudaGetSymbolAddress((void**)&pr,   g_pyr_ref);
    cudaGetSymbolAddress((void**)&ps,   g_pyr_supp);
    cudaGetSymbolAddress((void**)&bufA, g_bufA);
    cudaGetSymbolAddress((void**)&bufB, g_bufB);
    cudaGetSymbolAddress((void**)&flow, g_flow);
    cudaGetSymbolAddress((void**)&fup,  g_flowup);
    cudaGetSymbolAddress((void**)&bw,   g_bw);
    cudaGetSymbolAddress((void**)&bw1,  g_bw1);

    const int cins[5]   = {8, 32, 64, 32, 16};
    const int couts[5]  = {32, 64, 32, 16, 2};
    const int MIs[5]    = {4, 2, 4, 4, 4};
    const int nchs[5]   = {1, 2, 4, 2, 1};
    const int nchOs[5]  = {2, 4, 2, 1, 0};
    const int prefix[5] = {0, 6272, 31360, 56448, 62720};
    const int LT = 64288;

    int smem44 = 2 * 14 * (4 * 16 + 6) * 32;  // 62720
    int smem82 = 2 * 14 * (2 * 16 + 6) * 32;  // 34048
    int smemC1 = 2 * 14 * 70 * 16;            // 31360
    cudaFuncSetAttribute(k_conv7_mma<4, 4>, cudaFuncAttributeMaxDynamicSharedMemorySize, smem44);
    cudaFuncSetAttribute(k_conv7_mma<8, 2>, cudaFuncAttributeMaxDynamicSharedMemorySize, smem82);
    cudaFuncSetAttribute(k_conv7_mma<2, 4>, cudaFuncAttributeMaxDynamicSharedMemorySize, smem44);
    cudaFuncSetAttribute(k_conv7_mma<1, 4>, cudaFuncAttributeMaxDynamicSharedMemorySize, smem44);
    cudaFuncSetAttribute(k_conv1_mma8, cudaFuncAttributeMaxDynamicSharedMemorySize, smemC1);

    // ---- weight prep ----
    {
        int total = 4 * LT;
        k_wprep_all<<<(total + 255) / 256, 256>>>(Wt[0], Wt[1], Wt[2], Wt[3], Wt[4], bw);
        int t1 = 4 * 49 * 4 * 32;
        k_wprep1<<<(t1 + 255) / 256, 256>>>(Wt[0], bw1);
    }

    int off[6];
    {
        int o = 0;
        for (int l = 0; l < 6; l++) {
            off[l] = o;
            o += NB * 3 * (8 << l) * (14 << l);
        }
    }

    {
        int HW = 256 * 448;
        int total = NB * 3 * HW;
        k_normalize<<<(total + 255) / 256, 256>>>(ref, supp, pr + off[5], ps + off[5],
                                                  total, HW);
    }
    for (int l = 5; l >= 1; l--) {
        int H = 8 << (l - 1), W = 14 << (l - 1);
        int total = NB * 3 * H * W;
        int g = (total + 255) / 256;
        k_avgpool<<<g, 256>>>(pr + off[l], pr + off[l - 1], total, H, W);
        k_avgpool<<<g, 256>>>(ps + off[l], ps + off[l - 1], total, H, W);
    }

    for (int l = 0; l < 6; l++) {
        int H = 8 << l, W = 14 << l;
        int HW = H * W;

        int tp = NB * HW;
        k_prepare2<<<(tp + 255) / 256, 256>>>(pr + off[l], ps + off[l], flow, fup,
                                              bufA, H, W, (l == 0) ? 1 : 0,
                                              (l >= 2) ? 1 : 0);

        float* dst = (l == 5) ? (float*)d_out : flow;
        float* io[6] = {bufA, bufB, bufA, bufB, bufA, bufB};
        if (l < 2) {
            dim3 blk(16, 16);
            for (int i = 0; i < 5; i++) {
                int Cin = cins[i], Cout = couts[i];
                dim3 grd((W + 31) / 32, (H + 31) / 32, NB * ((Cout + CT - 1) / CT));
                const float* wp = Wt[i] + (size_t)l * Cout * Cin * 49;
                const float* bp = Bt[i] + (size_t)l * Cout;
                float* o = (i == 4) ? dst : io[i + 1];
                const float* rs = (i == 4) ? fup : nullptr;
                k_conv7<<<grd, blk>>>(io[i], wp, bp, o, rs, Cin, Cout, H, W,
                                      (i < 4) ? 1 : 0);
            }
        } else {
            int li = l - 2;
            for (int i = 0; i < 5; i++) {
                int Cout = couts[i];
                int TX = MIs[i] * 16;
                int nx = (W + TX - 1) / TX;
                dim3 grd(nx, H / 8, NB);
                const float* bp = Bt[i] + (size_t)l * Cout;
                const uint4* inp = (const uint4*)io[i];
                void* o = (i == 4) ? (void*)dst : (void*)io[i + 1];
                const float* rs = (i == 4) ? fup : nullptr;
                int out16 = (i < 4) ? 1 : 0;
                if (i == 0) {
                    const uint2* bw1p = bw1 + (size_t)li * 49 * 4 * 32;
                    k_conv1_mma8<<<grd, 256, smemC1>>>(inp, bw1p, bp,
                                                       (uint32_t*)io[1], H, W);
                } else {
                    const uint4* bwp = bw + (size_t)li * LT + prefix[i];
                    if (i == 1)
                        k_conv7_mma<8, 2><<<grd, 256, smem82>>>(inp, bwp, bp, o, rs,
                            nchs[i], nchOs[i], Cout, H, W, 1, out16);
                    else if (i == 2)
                        k_conv7_mma<4, 4><<<grd, 256, smem44>>>(inp, bwp, bp, o, rs,
                            nchs[i], nchOs[i], Cout, H, W, 1, out16);
                    else if (i == 3)
                        k_conv7_mma<2, 4><<<grd, 256, smem44>>>(inp, bwp, bp, o, rs,
                            nchs[i], nchOs[i], Cout, H, W, 1, out16);
                    else
                        k_conv7_mma<1, 4><<<grd, 256, smem44>>>(inp, bwp, bp, o, rs,
                            nchs[i], nchOs[i], Cout, H, W, 0, out16);
                }
            }
        }
    }
    (void)in_sizes; (void)n_in; (void)out_size;
}

// round 16
// speedup vs baseline: 1.0340x; 1.0125x over previous
#include <cuda_runtime.h>
#include <cuda_fp16.h>
#include <math.h>
#include <stdint.h>

#define NB 8   // batch

// ---------------- scratch (device globals; no allocation allowed) ----------------
__device__ float g_pyr_ref[3669120];
__device__ float g_pyr_supp[3669120];
__device__ float g_bufA[58720256];   // also used as fp16-split activation bytes
__device__ float g_bufB[58720256];
__device__ float g_flow[1835008];
__device__ float g_flowup[1835008];
__device__ uint4 g_bw[257152];   // fused hi/lo fp16 weight fragments, levels 2-5 (~4.1MB)
__device__ uint2 g_bw1[25088];   // conv1 k8 fragments, levels 2-5 (~200KB)

typedef unsigned long long u64;

// ---------------- packed f32x2 helpers (FFMA path, levels 0-1) ----------------
__device__ __forceinline__ u64 pack2(float lo, float hi) {
    u64 d; asm("mov.b64 %0, {%1, %2};" : "=l"(d) : "f"(lo), "f"(hi)); return d;
}
__device__ __forceinline__ u64 dup2(float v) {
    u64 d; asm("mov.b64 %0, {%1, %1};" : "=l"(d) : "f"(v)); return d;
}
__device__ __forceinline__ void unpack2(u64 v, float& lo, float& hi) {
    asm("mov.b64 {%0, %1}, %2;" : "=f"(lo), "=f"(hi) : "l"(v));
}
__device__ __forceinline__ void fma2(u64& d, u64 a, u64 b) {
    asm("fma.rn.f32x2 %0, %1, %2, %0;" : "+l"(d) : "l"(a), "l"(b));
}

// ---------------- mma helpers ----------------
__device__ __forceinline__ uint32_t smem_u32(const void* p) {
    uint32_t a;
    asm("{ .reg .u64 t; cvta.to.shared.u64 t, %1; cvt.u32.u64 %0, t; }" : "=r"(a) : "l"(p));
    return a;
}
__device__ __forceinline__ void ldmA(uint32_t* a, uint32_t addr) {
    asm volatile("ldmatrix.sync.aligned.m8n8.x4.shared.b16 {%0,%1,%2,%3}, [%4];"
                 : "=r"(a[0]), "=r"(a[1]), "=r"(a[2]), "=r"(a[3]) : "r"(addr));
}
__device__ __forceinline__ void ldmA2(uint32_t* a, uint32_t addr) {
    asm volatile("ldmatrix.sync.aligned.m8n8.x2.shared.b16 {%0,%1}, [%2];"
                 : "=r"(a[0]), "=r"(a[1]) : "r"(addr));
}
__device__ __forceinline__ void mma16816(float* c, const uint32_t* a, uint32_t b0, uint32_t b1) {
    asm volatile("mma.sync.aligned.m16n8k16.row.col.f32.f16.f16.f32 "
                 "{%0,%1,%2,%3}, {%4,%5,%6,%7}, {%8,%9}, {%0,%1,%2,%3};"
                 : "+f"(c[0]), "+f"(c[1]), "+f"(c[2]), "+f"(c[3])
                 : "r"(a[0]), "r"(a[1]), "r"(a[2]), "r"(a[3]), "r"(b0), "r"(b1));
}
__device__ __forceinline__ void mma1688(float* c, const uint32_t* a, uint32_t b0) {
    asm volatile("mma.sync.aligned.m16n8k8.row.col.f32.f16.f16.f32 "
                 "{%0,%1,%2,%3}, {%4,%5}, {%6}, {%0,%1,%2,%3};"
                 : "+f"(c[0]), "+f"(c[1]), "+f"(c[2]), "+f"(c[3])
                 : "r"(a[0]), "r"(a[1]), "r"(b0));
}
__device__ __forceinline__ uint32_t pack_h2(__half a, __half b) {
    __half2 h = __halves2half2(a, b);
    return *(uint32_t*)&h;
}
__device__ __forceinline__ void split16(float v, __half& h, __half& l) {
    h = __float2half_rn(v);
    l = __float2half_rn(v - __half2float(h));
}

// ---------------- small elementwise kernels ----------------
__global__ void k_normalize(const float* __restrict__ ref, const float* __restrict__ supp,
                            float* __restrict__ oref, float* __restrict__ osupp,
                            int total, int HW) {
    int i = blockIdx.x * blockDim.x + threadIdx.x;
    if (i >= total) return;
    int c = (i / HW) % 3;
    const float mean[3] = {0.485f, 0.456f, 0.406f};
    const float stdv[3] = {0.229f, 0.224f, 0.225f};
    oref[i]  = (ref[i]  - mean[c]) / stdv[c];
    osupp[i] = (supp[i] - mean[c]) / stdv[c];
}

// fused: one launch pools both ref and supp pyramids
__global__ void k_avgpool2(const float* __restrict__ inr, const float* __restrict__ ins,
                           float* __restrict__ outr, float* __restrict__ outs,
                           int total, int H, int W) {
    int i = blockIdx.x * blockDim.x + threadIdx.x;
    if (i >= total) return;
    int x = i % W;
    int y = (i / W) % H;
    int nc = i / (W * H);
    size_t so = (size_t)nc * (4 * H * W) + (size_t)(2 * y) * (2 * W) + 2 * x;
    const float* p = inr + so;
    outr[i] = 0.25f * (p[0] + p[1] + p[2 * W] + p[2 * W + 1]);
    p = ins + so;
    outs[i] = 0.25f * (p[0] + p[1] + p[2 * W] + p[2 * W + 1]);
}

// fused: flow upsample + warp + concat; out = fp32 NCHW (out16=0) or compact fp16-split
// 32B/pixel blocks {hi 16B, lo 16B} (out16=1, consumed by conv1-k8)
__global__ void k_prepare2(const float* __restrict__ r, const float* __restrict__ s,
                           const float* __restrict__ flowc, float* __restrict__ fup,
                           void* __restrict__ outv, int H, int W, int lvl0, int out16) {
    int HW = H * W;
    int total = NB * HW;
    int i = blockIdx.x * blockDim.x + threadIdx.x;
    if (i >= total) return;
    int x = i % W;
    int y = (i / W) % H;
    int n = i / HW;
    int pix = y * W + x;

    float f0, f1;
    if (lvl0) {
        f0 = 0.f; f1 = 0.f;
    } else {
        int h = H / 2, w = W / 2;
        float ys = (float)(h - 1) * (float)y / (float)(H - 1);
        float xsf = (float)(w - 1) * (float)x / (float)(W - 1);
        int yy0 = (int)floorf(ys), xx0 = (int)floorf(xsf);
        float wyv = ys - (float)yy0, wxv = xsf - (float)xx0;
        int yy1 = min(yy0 + 1, h - 1), xx1 = min(xx0 + 1, w - 1);
        const float* p0 = flowc + (size_t)(n * 2 + 0) * h * w;
        const float* p1 = p0 + (size_t)h * w;
        {
            float a = p0[yy0 * w + xx0] * (1.f - wyv) + p0[yy1 * w + xx0] * wyv;
            float b = p0[yy0 * w + xx1] * (1.f - wyv) + p0[yy1 * w + xx1] * wyv;
            f0 = 2.0f * (a * (1.f - wxv) + b * wxv);
        }
        {
            float a = p1[yy0 * w + xx0] * (1.f - wyv) + p1[yy1 * w + xx0] * wyv;
            float b = p1[yy0 * w + xx1] * (1.f - wyv) + p1[yy1 * w + xx1] * wyv;
            f1 = 2.0f * (a * (1.f - wxv) + b * wxv);
        }
    }
    fup[((size_t)n * 2 + 0) * HW + pix] = f0;
    fup[((size_t)n * 2 + 1) * HW + pix] = f1;

    float fx = fminf(fmaxf((float)x + f0, 0.f), (float)(W - 1));
    float fy = fminf(fmaxf((float)y + f1, 0.f), (float)(H - 1));
    int x0 = (int)floorf(fx), y0 = (int)floorf(fy);
    int x1 = min(x0 + 1, W - 1), y1 = min(y0 + 1, H - 1);
    float wx = fx - (float)x0, wy = fy - (float)y0;

    float v[8];
#pragma unroll
    for (int c = 0; c < 3; c++) {
        v[c] = r[((size_t)n * 3 + c) * HW + pix];
        const float* sp = s + ((size_t)n * 3 + c) * HW;
        v[3 + c] = sp[y0 * W + x0] * (1.f - wy) * (1.f - wx)
                 + sp[y0 * W + x1] * (1.f - wy) * wx
                 + sp[y1 * W + x0] * wy * (1.f - wx)
                 + sp[y1 * W + x1] * wy * wx;
    }
    v[6] = f0; v[7] = f1;

    if (!out16) {
        float* o = (float*)outv + (size_t)n * 8 * HW + pix;
#pragma unroll
        for (int c = 0; c < 8; c++) o[(size_t)c * HW] = v[c];
    } else {
        uint32_t hw[4], lw[4];
#pragma unroll
        for (int j = 0; j < 4; j++) {
            __half h0, l0, h1, l1;
            split16(v[2 * j], h0, l0);
            split16(v[2 * j + 1], h1, l1);
            hw[j] = pack_h2(h0, h1);
            lw[j] = pack_h2(l0, l1);
        }
        uint4* o = (uint4*)outv + (((size_t)n * H + y) * W + x) * 2;
        o[0] = make_uint4(hw[0], hw[1], hw[2], hw[3]);
        o[1] = make_uint4(lw[0], lw[1], lw[2], lw[3]);
    }
}

// ---------------- weight prep (levels 2-5, convs 2-5 k16 path) ----------------
__global__ void k_wprep_all(const float* __restrict__ w1, const float* __restrict__ w2,
                            const float* __restrict__ w3, const float* __restrict__ w4,
                            const float* __restrict__ w5, uint4* __restrict__ dst) {
    const int LT = 64288;
    int idx = blockIdx.x * blockDim.x + threadIdx.x;
    if (idx >= 4 * LT) return;
    int li = idx / LT;   // 0..3 -> levels 2..5
    int rem = idx % LT;
    const int tot[5]   = {6272, 25088, 25088, 6272, 1568};
    const int cins[5]  = {8, 32, 64, 32, 16};
    const int couts[5] = {32, 64, 32, 16, 2};
    const int NFs[5]   = {4, 8, 4, 2, 1};
    const float* ws[5] = {w1, w2, w3, w4, w5};
    int ci_ = 0;
    while (ci_ < 4 && rem >= tot[ci_]) { rem -= tot[ci_]; ci_++; }
    if (ci_ == 0) { dst[idx] = make_uint4(0, 0, 0, 0); return; }  // conv1 handled by k8 prep
    int Cin = cins[ci_], Cout = couts[ci_], NF = NFs[ci_];
    const float* w = ws[ci_] + (size_t)(2 + li) * Cout * Cin * 49;

    int lane = rem & 31;
    int i2 = rem >> 5;
    int nf = i2 % NF;   i2 /= NF;
    int tap = i2 % 49;
    int chunk = i2 / 49;
    int n = nf * 8 + (lane >> 2);
    int k0 = chunk * 16 + (lane & 3) * 2;
    float v[4];
#pragma unroll
    for (int j = 0; j < 4; j++) {
        int k = k0 + (j >> 1) * 8 + (j & 1);
        v[j] = (n < Cout && k < Cin) ? w[((size_t)n * Cin + k) * 49 + tap] : 0.f;
    }
    __half hh[4], hl[4];
#pragma unroll
    for (int j = 0; j < 4; j++) {
        __half hi = __float2half_rn(v[j]);
        hh[j] = hi;
        hl[j] = __float2half_rn(v[j] - __half2float(hi));
    }
    dst[idx] = make_uint4(pack_h2(hh[0], hh[1]), pack_h2(hh[2], hh[3]),
                          pack_h2(hl[0], hl[1]), pack_h2(hl[2], hl[3]));
}

// conv1 k8 fragments: [li 4][tap 49][nf 4][lane 32] -> uint2 {b0_hi, b0_lo}
__global__ void k_wprep1(const float* __restrict__ w1, uint2* __restrict__ dst) {
    int idx = blockIdx.x * blockDim.x + threadIdx.x;
    if (idx >= 4 * 49 * 4 * 32) return;
    int lane = idx & 31;
    int i2 = idx >> 5;
    int nf = i2 % 4;   i2 /= 4;
    int tap = i2 % 49;
    int li = i2 / 49;
    const float* w = w1 + (size_t)(2 + li) * 32 * 8 * 49;
    int n = nf * 8 + (lane >> 2);
    int k0 = (lane & 3) * 2;
    float v0 = w[((size_t)n * 8 + k0) * 49 + tap];
    float v1 = w[((size_t)n * 8 + k0 + 1) * 49 + tap];
    __half h0, l0, h1, l1;
    split16(v0, h0, l0);
    split16(v1, h1, l1);
    dst[idx] = make_uint2(pack_h2(h0, h1), pack_h2(l0, l1));
}

// ---------------- conv1: k8 mma (Cin=8, Cout=32), levels 2-5 ----------------
__global__ void __launch_bounds__(256, 2)
k_conv1_mma8(const uint4* __restrict__ in, const uint2* __restrict__ bw,
             const float* __restrict__ bias, uint32_t* __restrict__ ob,
             int H, int W) {
    constexpr int MI = 4, NF = 4;
    constexpr int TX = 64, TW = 70;
    constexpr int PART = 14 * TW * 16;   // 15680 bytes per part
    extern __shared__ char smem[];
    uint32_t A0 = smem_u32(smem);

    int tid = threadIdx.x;
    int wid = tid >> 5;
    int lane = tid & 31;

    int x0 = blockIdx.x * TX;
    if (x0 > W - TX) x0 = W - TX;
    if (x0 < 0) x0 = 0;
    int y0 = blockIdx.y * 8;
    int n  = blockIdx.z;

    float C[MI][NF][4];
#pragma unroll
    for (int mi = 0; mi < MI; mi++)
#pragma unroll
        for (int nf = 0; nf < NF; nf++)
#pragma unroll
            for (int j = 0; j < 4; j++) C[mi][nf][j] = 0.f;

    // build: 16B hi + 16B lo per pixel (no swizzle needed: 8 rows = 128B line)
    const uint4* ipc = in + ((size_t)n * H * W) * 2;
    for (int idx = tid; idx < 14 * TW; idx += 256) {
        int r = idx / TW, xt = idx % TW;
        int iy = y0 - 3 + r;
        int ix = x0 - 3 + xt;
        uint4 h = make_uint4(0, 0, 0, 0), l = h;
        if (iy >= 0 && iy < H && ix >= 0 && ix < W) {
            const uint4* sp = ipc + ((size_t)iy * W + ix) * 2;
            h = sp[0]; l = sp[1];
        }
        *(uint4*)(smem + (size_t)idx * 16) = h;
        *(uint4*)(smem + PART + (size_t)idx * 16) = l;
    }
    __syncthreads();

#pragma unroll 1
    for (int tap = 0; tap < 49; tap++) {
        int dy = tap / 7, dx = tap % 7;
        int pixrow = (wid + dy) * TW + dx + (lane & 15);
        uint32_t ah[MI][2], al[MI][2];
#pragma unroll
        for (int mi = 0; mi < MI; mi++) {
            uint32_t at = A0 + (uint32_t)(pixrow + mi * 16) * 16;
            ldmA2(ah[mi], at);
            ldmA2(al[mi], at + PART);
        }
        const uint2* bt = bw + (size_t)tap * NF * 32;
#pragma unroll
        for (int nf = 0; nf < NF; nf++) {
            uint2 wv = bt[nf * 32 + lane];
#pragma unroll
            for (int mi = 0; mi < MI; mi++) {
                mma1688(C[mi][nf], ah[mi], wv.x);
                mma1688(C[mi][nf], ah[mi], wv.y);
                mma1688(C[mi][nf], al[mi], wv.x);
            }
        }
    }

    int y = y0 + wid;
#pragma unroll
    for (int nf = 0; nf < NF; nf++) {
        int c = nf * 8 + (lane & 3) * 2;
        int ch = c >> 4;
        int wd = (c & 15) >> 1;
        float b0 = bias[c], b1 = bias[c + 1];
        size_t rowbase = (((size_t)(n * 2 + ch) * H + y) * W) * 16;
#pragma unroll
        for (int mi = 0; mi < MI; mi++) {
            int xA = x0 + mi * 16 + (lane >> 2);
            float r0 = fmaxf(C[mi][nf][0] + b0, 0.f);
            float r1 = fmaxf(C[mi][nf][1] + b1, 0.f);
            float r2 = fmaxf(C[mi][nf][2] + b0, 0.f);
            float r3 = fmaxf(C[mi][nf][3] + b1, 0.f);
            __half h0, l0, h1, l1, h2, l2, h3, l3;
            split16(r0, h0, l0); split16(r1, h1, l1);
            split16(r2, h2, l2); split16(r3, h3, l3);
            if (xA < W) {
                size_t pb = rowbase + (size_t)xA * 16;
                ob[pb + wd]     = pack_h2(h0, h1);
                ob[pb + 8 + wd] = pack_h2(l0, l1);
            }
            if (xA + 8 < W) {
                size_t pb2 = rowbase + (size_t)(xA + 8) * 16;
                ob[pb2 + wd]     = pack_h2(h2, h3);
                ob[pb2 + 8 + wd] = pack_h2(l2, l3);
            }
        }
    }
}

// ---------------- mma implicit-GEMM 7x7 conv, k16 path (convs 2-5, levels 2-5) ----------------
template <int NF, int MI>
__global__ void __launch_bounds__(256, 2)
k_conv7_mma(const uint4* __restrict__ in, const uint4* __restrict__ bw,
            const float* __restrict__ bias, void* __restrict__ outv,
            const float* __restrict__ resid,
            int nch, int nchO, int Cout, int H, int W, int relu, int out16) {
    constexpr int TX = MI * 16;
    constexpr int TW = TX + 6;
    constexpr int PART = 14 * TW * 32;
    extern __shared__ char smem[];
    uint32_t A0 = smem_u32(smem);

    int tid = threadIdx.x;
    int wid = tid >> 5;
    int lane = tid & 31;

    int x0 = blockIdx.x * TX;
    if (x0 > W - TX) x0 = W - TX;
    if (x0 < 0) x0 = 0;
    int y0 = blockIdx.y * 8;
    int n  = blockIdx.z;

    float C[MI][NF][4];
#pragma unroll
    for (int mi = 0; mi < MI; mi++)
#pragma unroll
        for (int nf = 0; nf < NF; nf++)
#pragma unroll
            for (int j = 0; j < 4; j++) C[mi][nf][j] = 0.f;

    for (int chunk = 0; chunk < nch; chunk++) {
        const uint4* ipc = in + (size_t)(n * nch + chunk) * H * W * 4;
        for (int idx = tid; idx < 14 * TW; idx += 256) {
            int r = idx / TW, xt = idx % TW;
            int iy = y0 - 3 + r;
            int ix = x0 - 3 + xt;
            uint4 h0 = make_uint4(0, 0, 0, 0), h1 = h0, l0 = h0, l1 = h0;
            if (iy >= 0 && iy < H && ix >= 0 && ix < W) {
                const uint4* sp = ipc + ((size_t)iy * W + ix) * 4;
                h0 = sp[0]; h1 = sp[1]; l0 = sp[2]; l1 = sp[3];
            }
            int s = (idx >> 2) & 1;
            uint4* p0 = (uint4*)(smem + (size_t)idx * 32);
            uint4* p1 = (uint4*)(smem + PART + (size_t)idx * 32);
            p0[s]     = h0;
            p0[s ^ 1] = h1;
            p1[s]     = l0;
            p1[s ^ 1] = l1;
        }
        __syncthreads();

        const uint4* bwc = bw + (size_t)chunk * 49 * NF * 32;

#pragma unroll 1
        for (int tap = 0; tap < 49; tap++) {
            int dy = tap / 7, dx = tap % 7;
            int pixrow = (wid + dy) * TW + dx + (lane & 15);
            uint32_t hsel = (((uint32_t)lane >> 4) ^ (((uint32_t)pixrow >> 2) & 1)) << 4;
            uint32_t ah[MI][4], al[MI][4];
#pragma unroll
            for (int mi = 0; mi < MI; mi++) {
                uint32_t at = A0 + (uint32_t)(pixrow + mi * 16) * 32 + hsel;
                ldmA(ah[mi], at);
                ldmA(al[mi], at + PART);
            }
            const uint4* bt = bwc + (size_t)tap * NF * 32;
#pragma unroll
            for (int nf = 0; nf < NF; nf++) {
                uint4 wv = bt[nf * 32 + lane];
#pragma unroll
                for (int mi = 0; mi < MI; mi++) {
                    mma16816(C[mi][nf], ah[mi], wv.x, wv.y);
                    mma16816(C[mi][nf], ah[mi], wv.z, wv.w);
                    mma16816(C[mi][nf], al[mi], wv.x, wv.y);
                }
            }
        }
        if (chunk + 1 < nch) __syncthreads();
    }

    int y = y0 + wid;
    if (out16) {
        uint32_t* ob = (uint32_t*)outv;
#pragma unroll
        for (int nf = 0; nf < NF; nf++) {
            int c = nf * 8 + (lane & 3) * 2;
            int ch = c >> 4;
            int wd = (c & 15) >> 1;
            float b0 = bias[c], b1 = bias[c + 1];
            size_t rowbase = (((size_t)(n * nchO + ch) * H + y) * W) * 16;
#pragma unroll
            for (int mi = 0; mi < MI; mi++) {
                int xA = x0 + mi * 16 + (lane >> 2);
                float r0 = C[mi][nf][0] + b0;
                float r1 = C[mi][nf][1] + b1;
                float r2 = C[mi][nf][2] + b0;
                float r3 = C[mi][nf][3] + b1;
                if (relu) {
                    r0 = fmaxf(r0, 0.f); r1 = fmaxf(r1, 0.f);
                    r2 = fmaxf(r2, 0.f); r3 = fmaxf(r3, 0.f);
                }
                __half h0, l0, h1, l1, h2, l2, h3, l3;
                split16(r0, h0, l0); split16(r1, h1, l1);
                split16(r2, h2, l2); split16(r3, h3, l3);
                if (xA < W) {
                    size_t pb = rowbase + (size_t)xA * 16;
                    ob[pb + wd]     = pack_h2(h0, h1);
                    ob[pb + 8 + wd] = pack_h2(l0, l1);
                }
                if (xA + 8 < W) {
                    size_t pb2 = rowbase + (size_t)(xA + 8) * 16;
                    ob[pb2 + wd]     = pack_h2(h2, h3);
                    ob[pb2 + 8 + wd] = pack_h2(l2, l3);
                }
            }
        }
    } else {
        float* out = (float*)outv;
#pragma unroll
        for (int nf = 0; nf < NF; nf++) {
            int c = nf * 8 + (lane & 3) * 2;
            bool v0 = c < Cout, v1 = c + 1 < Cout;
            float b0 = v0 ? bias[c] : 0.f;
            float b1 = v1 ? bias[c + 1] : 0.f;
            size_t off0 = ((size_t)(n * Cout + c) * H + y) * W;
            float* o0 = out + off0;
            float* o1 = o0 + (size_t)H * W;
            const float* rr0 = resid ? resid + off0 : nullptr;
            const float* rr1 = rr0 + (size_t)H * W;
#pragma unroll
            for (int mi = 0; mi < MI; mi++) {
                int xA = x0 + mi * 16 + (lane >> 2);
                float r0 = C[mi][nf][0] + b0;
                float r1 = C[mi][nf][1] + b1;
                float r2 = C[mi][nf][2] + b0;
                float r3 = C[mi][nf][3] + b1;
                if (relu) {
                    r0 = fmaxf(r0, 0.f); r1 = fmaxf(r1, 0.f);
                    r2 = fmaxf(r2, 0.f); r3 = fmaxf(r3, 0.f);
                }
                if (resid) {
                    if (xA < W) {
                        if (v0) r0 += rr0[xA];
                        if (v1) r1 += rr1[xA];
                    }
                    if (xA + 8 < W) {
                        if (v0) r2 += rr0[xA + 8];
                        if (v1) r3 += rr1[xA + 8];
                    }
                }
                if (xA < W) {
                    if (v0) o0[xA] = r0;
                    if (v1) o1[xA] = r1;
                }
                if (xA + 8 < W) {
                    if (v0) o0[xA + 8] = r2;
                    if (v1) o1[xA + 8] = r3;
                }
            }
        }
    }
}

// ---------------- FFMA f32x2 conv (levels 0-1) ----------------
#define CT 8
__global__ __launch_bounds__(256) void k_conv7(
    const float* __restrict__ in, const float* __restrict__ w,
    const float* __restrict__ bias, float* __restrict__ out,
    const float* __restrict__ resid,
    int Cin, int Cout, int H, int W, int relu) {
    __shared__ __align__(16) float s_in[38 * 40];
    __shared__ __align__(16) float s_w[49][CT];

    int coutGroups = (Cout + CT - 1) / CT;
    int cg = blockIdx.z % coutGroups;
    int n  = blockIdx.z / coutGroups;
    int ox0 = blockIdx.x * 32;
    int oy0 = blockIdx.y * 32;
    int tx = threadIdx.x, ty = threadIdx.y;
    int tid = ty * 16 + tx;

    u64 acc[4][CT / 2];
#pragma unroll
    for (int j = 0; j < CT / 2; j++) {
        int c0 = cg * CT + 2 * j, c1 = c0 + 1;
        float b0 = (c0 < Cout) ? bias[c0] : 0.f;
        float b1 = (c1 < Cout) ? bias[c1] : 0.f;
        u64 b = pack2(b0, b1);
        acc[0][j] = b; acc[1][j] = b; acc[2][j] = b; acc[3][j] = b;
    }

    const float2* s_in2 = (const float2*)s_in;

    for (int ci = 0; ci < Cin; ci++) {
        const float* ip = in + (size_t)(n * Cin + ci) * H * W;
        for (int idx = tid; idx < 38 * 38; idx += 256) {
            int ly = idx / 38, lx = idx % 38;
            int iy = oy0 - 3 + ly, ix = ox0 - 3 + lx;
            s_in[ly * 40 + lx] = (iy >= 0 && iy < H && ix >= 0 && ix < W)
                                     ? ip[(size_t)iy * W + ix] : 0.f;
        }
        for (int idx = tid; idx < CT * 49; idx += 256) {
            int co = idx / 49, k = idx % 49;
            int cout = cg * CT + co;
            s_w[k][co] = (cout < Cout) ? w[((size_t)cout * Cin + ci) * 49 + k] : 0.f;
        }
        __syncthreads();

        float ra[8], rb[8];
        {
            int base2 = ((ty * 2) * 40 + tx * 2) >> 1;
#pragma unroll
            for (int j = 0; j < 4; j++) {
                float2 t = s_in2[base2 + j];
                ra[2 * j] = t.x; ra[2 * j + 1] = t.y;
            }
        }
#pragma unroll
        for (int ky = 0; ky < 7; ky++) {
            int base2 = ((ty * 2 + ky + 1) * 40 + tx * 2) >> 1;
#pragma unroll
            for (int j = 0; j < 4; j++) {
                float2 t = s_in2[base2 + j];
                rb[2 * j] = t.x; rb[2 * j + 1] = t.y;
            }
            u64 da = dup2(ra[0]);
            u64 db = dup2(rb[0]);
#pragma unroll
            for (int kx = 0; kx < 7; kx++) {
                u64 da1 = dup2(ra[kx + 1]);
                u64 db1 = dup2(rb[kx + 1]);
                const u64* wp = (const u64*)&s_w[ky * 7 + kx][0];
#pragma unroll
                for (int j = 0; j < CT / 2; j++) {
                    u64 wv = wp[j];
                    fma2(acc[0][j], da,  wv);
                    fma2(acc[1][j], da1, wv);
                    fma2(acc[2][j], db,  wv);
                    fma2(acc[3][j], db1, wv);
                }
                da = da1; db = db1;
            }
#pragma unroll
            for (int j = 0; j < 8; j++) ra[j] = rb[j];
        }
        __syncthreads();
    }

    int oy = oy0 + ty * 2, ox = ox0 + tx * 2;
#pragma unroll
    for (int j = 0; j < CT / 2; j++) {
        int c0 = cg * CT + 2 * j;
#pragma unroll
        for (int p = 0; p < 4; p++) {
            int yy = oy + (p >> 1), xx = ox + (p & 1);
            if (yy < H && xx < W) {
                float v0, v1;
                unpack2(acc[p][j], v0, v1);
                if (relu) { v0 = fmaxf(v0, 0.f); v1 = fmaxf(v1, 0.f); }
                if (c0 < Cout) {
                    size_t o = (size_t)(n * Cout + c0) * H * W + (size_t)yy * W + xx;
                    out[o] = resid ? (v0 + resid[o]) : v0;
                }
                if (c0 + 1 < Cout) {
                    size_t o = (size_t)(n * Cout + c0 + 1) * H * W + (size_t)yy * W + xx;
                    out[o] = resid ? (v1 + resid[o]) : v1;
                }
            }
        }
    }
}

// ---------------- driver ----------------
extern "C" void kernel_launch(void* const* d_in, const int* in_sizes, int n_in,
                              void* d_out, int out_size) {
    const float* ref  = (const float*)d_in[0];
    const float* supp = (const float*)d_in[1];
    const float* Wt[5] = {(const float*)d_in[2], (const float*)d_in[4],
                          (const float*)d_in[6], (const float*)d_in[8],
                          (const float*)d_in[10]};
    const float* Bt[5] = {(const float*)d_in[3], (const float*)d_in[5],
                          (const float*)d_in[7], (const float*)d_in[9],
                          (const float*)d_in[11]};

    float *pr, *ps, *bufA, *bufB, *flow, *fup;
    uint4* bw;
    uint2* bw1;
    cudaGetSymbolAddress((void**)&pr,   g_pyr_ref);
    cudaGetSymbolAddress((void**)&ps,   g_pyr_supp);
    cudaGetSymbolAddress((void**)&bufA, g_bufA);
    cudaGetSymbolAddress((void**)&bufB, g_bufB);
    cudaGetSymbolAddress((void**)&flow, g_flow);
    cudaGetSymbolAddress((void**)&fup,  g_flowup);
    cudaGetSymbolAddress((void**)&bw,   g_bw);
    cudaGetSymbolAddress((void**)&bw1,  g_bw1);

    const int couts[5]  = {32, 64, 32, 16, 2};
    const int cins[5]   = {8, 32, 64, 32, 16};
    const int nchs[5]   = {1, 2, 4, 2, 1};
    const int nchOs[5]  = {2, 4, 2, 1, 0};
    const int prefix[5] = {0, 6272, 31360, 56448, 62720};
    const int LT = 64288;

    int smem44 = 2 * 14 * (4 * 16 + 6) * 32;  // 62720
    int smem82 = 2 * 14 * (2 * 16 + 6) * 32;  // 34048
    int smemC1 = 2 * 14 * 70 * 16;            // 31360
    cudaFuncSetAttribute(k_conv7_mma<4, 4>, cudaFuncAttributeMaxDynamicSharedMemorySize, smem44);
    cudaFuncSetAttribute(k_conv7_mma<8, 2>, cudaFuncAttributeMaxDynamicSharedMemorySize, smem82);
    cudaFuncSetAttribute(k_conv7_mma<2, 4>, cudaFuncAttributeMaxDynamicSharedMemorySize, smem44);
    cudaFuncSetAttribute(k_conv7_mma<1, 4>, cudaFuncAttributeMaxDynamicSharedMemorySize, smem44);
    cudaFuncSetAttribute(k_conv7_mma<4, 2>, cudaFuncAttributeMaxDynamicSharedMemorySize, smem82);
    cudaFuncSetAttribute(k_conv7_mma<2, 2>, cudaFuncAttributeMaxDynamicSharedMemorySize, smem82);
    cudaFuncSetAttribute(k_conv7_mma<1, 2>, cudaFuncAttributeMaxDynamicSharedMemorySize, smem82);
    cudaFuncSetAttribute(k_conv1_mma8, cudaFuncAttributeMaxDynamicSharedMemorySize, smemC1);

    // ---- weight prep ----
    {
        int total = 4 * LT;
        k_wprep_all<<<(total + 255) / 256, 256>>>(Wt[0], Wt[1], Wt[2], Wt[3], Wt[4], bw);
        int t1 = 4 * 49 * 4 * 32;
        k_wprep1<<<(t1 + 255) / 256, 256>>>(Wt[0], bw1);
    }

    int off[6];
    {
        int o = 0;
        for (int l = 0; l < 6; l++) {
            off[l] = o;
            o += NB * 3 * (8 << l) * (14 << l);
        }
    }

    {
        int HW = 256 * 448;
        int total = NB * 3 * HW;
        k_normalize<<<(total + 255) / 256, 256>>>(ref, supp, pr + off[5], ps + off[5],
                                                  total, HW);
    }
    for (int l = 5; l >= 1; l--) {
        int H = 8 << (l - 1), W = 14 << (l - 1);
        int total = NB * 3 * H * W;
        int g = (total + 255) / 256;
        k_avgpool2<<<g, 256>>>(pr + off[l], ps + off[l], pr + off[l - 1], ps + off[l - 1],
                               total, H, W);
    }

    for (int l = 0; l < 6; l++) {
        int H = 8 << l, W = 14 << l;
        int HW = H * W;

        int tp = NB * HW;
        k_prepare2<<<(tp + 255) / 256, 256>>>(pr + off[l], ps + off[l], flow, fup,
                                              bufA, H, W, (l == 0) ? 1 : 0,
                                              (l >= 2) ? 1 : 0);

        float* dst = (l == 5) ? (float*)d_out : flow;
        float* io[6] = {bufA, bufB, bufA, bufB, bufA, bufB};
        if (l < 2) {
            dim3 blk(16, 16);
            for (int i = 0; i < 5; i++) {
                int Cin = cins[i], Cout = couts[i];
                dim3 grd((W + 31) / 32, (H + 31) / 32, NB * ((Cout + CT - 1) / CT));
                const float* wp = Wt[i] + (size_t)l * Cout * Cin * 49;
                const float* bp = Bt[i] + (size_t)l * Cout;
                float* o = (i == 4) ? dst : io[i + 1];
                const float* rs = (i == 4) ? fup : nullptr;
                k_conv7<<<grd, blk>>>(io[i], wp, bp, o, rs, Cin, Cout, H, W,
                                      (i < 4) ? 1 : 0);
            }
        } else {
            int li = l - 2;
            // level 3 uses MI=2 for convs 3-5 (occupancy); others MI=4
            int mi34 = (l == 3) ? 2 : 4;
            for (int i = 0; i < 5; i++) {
                int Cout = couts[i];
                int MI = (i == 1) ? 2 : ((i == 0) ? 4 : mi34);
                int TX = MI * 16;
                int nx = (W + TX - 1) / TX;
                dim3 grd(nx, H / 8, NB);
                const float* bp = Bt[i] + (size_t)l * Cout;
                const uint4* inp = (const uint4*)io[i];
                void* o = (i == 4) ? (void*)dst : (void*)io[i + 1];
                const float* rs = (i == 4) ? fup : nullptr;
                int out16 = (i < 4) ? 1 : 0;
                if (i == 0) {
                    const uint2* bw1p = bw1 + (size_t)li * 49 * 4 * 32;
                    k_conv1_mma8<<<grd, 256, smemC1>>>(inp, bw1p, bp,
                                                       (uint32_t*)io[1], H, W);
                } else {
                    const uint4* bwp = bw + (size_t)li * LT + prefix[i];
                    int sm = (MI == 2) ? smem82 : smem44;
                    if (i == 1)
                        k_conv7_mma<8, 2><<<grd, 256, smem82>>>(inp, bwp, bp, o, rs,
                            nchs[i], nchOs[i], Cout, H, W, 1, out16);
                    else if (i == 2) {
                        if (MI == 2)
                            k_conv7_mma<4, 2><<<grd, 256, sm>>>(inp, bwp, bp, o, rs,
                                nchs[i], nchOs[i], Cout, H, W, 1, out16);
                        else
                            k_conv7_mma<4, 4><<<grd, 256, sm>>>(inp, bwp, bp, o, rs,
                                nchs[i], nchOs[i], Cout, H, W, 1, out16);
                    } else if (i == 3) {
                        if (MI == 2)
                            k_conv7_mma<2, 2><<<grd, 256, sm>>>(inp, bwp, bp, o, rs,
                                nchs[i], nchOs[i], Cout, H, W, 1, out16);
                        else
                            k_conv7_mma<2, 4><<<grd, 256, sm>>>(inp, bwp, bp, o, rs,
                                nchs[i], nchOs[i], Cout, H, W, 1, out16);
                    } else {
                        if (MI == 2)
                            k_conv7_mma<1, 2><<<grd, 256, sm>>>(inp, bwp, bp, o, rs,
                                nchs[i], nchOs[i], Cout, H, W, 0, out16);
                        else
                            k_conv7_mma<1, 4><<<grd, 256, sm>>>(inp, bwp, bp, o, rs,
                                nchs[i], nchOs[i], Cout, H, W, 0, out16);
                    }
                }
            }
        }
    }
    (void)in_sizes; (void)n_in; (void)out_size;
}

// round 17
// speedup vs baseline: 1.0476x; 1.0132x over previous
#include <cuda_runtime.h>
#include <cuda_fp16.h>
#include <math.h>
#include <stdint.h>

#define NB 8   // batch

// ---------------- scratch (device globals; no allocation allowed) ----------------
__device__ float g_pyr_ref[3669120];
__device__ float g_pyr_supp[3669120];
__device__ float g_bufA[58720256];   // also used as fp16-split activation bytes
__device__ float g_bufB[58720256];
__device__ float g_flow[1835008];
__device__ float g_flowup[1835008];
__device__ uint4 g_bw[257152];   // fused hi/lo fp16 weight fragments, levels 2-5 (~4.1MB)
__device__ uint2 g_bw1[25088];   // conv1 k8 fragments, levels 2-5 (~200KB)

typedef unsigned long long u64;

// ---------------- packed f32x2 helpers (FFMA path, levels 0-1) ----------------
__device__ __forceinline__ u64 pack2(float lo, float hi) {
    u64 d; asm("mov.b64 %0, {%1, %2};" : "=l"(d) : "f"(lo), "f"(hi)); return d;
}
__device__ __forceinline__ u64 dup2(float v) {
    u64 d; asm("mov.b64 %0, {%1, %1};" : "=l"(d) : "f"(v)); return d;
}
__device__ __forceinline__ void unpack2(u64 v, float& lo, float& hi) {
    asm("mov.b64 {%0, %1}, %2;" : "=f"(lo), "=f"(hi) : "l"(v));
}
__device__ __forceinline__ void fma2(u64& d, u64 a, u64 b) {
    asm("fma.rn.f32x2 %0, %1, %2, %0;" : "+l"(d) : "l"(a), "l"(b));
}

// ---------------- mma helpers ----------------
__device__ __forceinline__ uint32_t smem_u32(const void* p) {
    uint32_t a;
    asm("{ .reg .u64 t; cvta.to.shared.u64 t, %1; cvt.u32.u64 %0, t; }" : "=r"(a) : "l"(p));
    return a;
}
__device__ __forceinline__ void ldmA(uint32_t* a, uint32_t addr) {
    asm volatile("ldmatrix.sync.aligned.m8n8.x4.shared.b16 {%0,%1,%2,%3}, [%4];"
                 : "=r"(a[0]), "=r"(a[1]), "=r"(a[2]), "=r"(a[3]) : "r"(addr));
}
__device__ __forceinline__ void ldmA2(uint32_t* a, uint32_t addr) {
    asm volatile("ldmatrix.sync.aligned.m8n8.x2.shared.b16 {%0,%1}, [%2];"
                 : "=r"(a[0]), "=r"(a[1]) : "r"(addr));
}
__device__ __forceinline__ void mma16816(float* c, const uint32_t* a, uint32_t b0, uint32_t b1) {
    asm volatile("mma.sync.aligned.m16n8k16.row.col.f32.f16.f16.f32 "
                 "{%0,%1,%2,%3}, {%4,%5,%6,%7}, {%8,%9}, {%0,%1,%2,%3};"
                 : "+f"(c[0]), "+f"(c[1]), "+f"(c[2]), "+f"(c[3])
                 : "r"(a[0]), "r"(a[1]), "r"(a[2]), "r"(a[3]), "r"(b0), "r"(b1));
}
__device__ __forceinline__ void mma1688(float* c, const uint32_t* a, uint32_t b0) {
    asm volatile("mma.sync.aligned.m16n8k8.row.col.f32.f16.f16.f32 "
                 "{%0,%1,%2,%3}, {%4,%5}, {%6}, {%0,%1,%2,%3};"
                 : "+f"(c[0]), "+f"(c[1]), "+f"(c[2]), "+f"(c[3])
                 : "r"(a[0]), "r"(a[1]), "r"(b0));
}
__device__ __forceinline__ uint32_t pack_h2(__half a, __half b) {
    __half2 h = __halves2half2(a, b);
    return *(uint32_t*)&h;
}
__device__ __forceinline__ void split16(float v, __half& h, __half& l) {
    h = __float2half_rn(v);
    l = __float2half_rn(v - __half2float(h));
}

// ---------------- small elementwise kernels ----------------
__global__ void k_normalize(const float* __restrict__ ref, const float* __restrict__ supp,
                            float* __restrict__ oref, float* __restrict__ osupp,
                            int total, int HW) {
    int i = blockIdx.x * blockDim.x + threadIdx.x;
    if (i >= total) return;
    int c = (i / HW) % 3;
    const float mean[3] = {0.485f, 0.456f, 0.406f};
    const float stdv[3] = {0.229f, 0.224f, 0.225f};
    oref[i]  = (ref[i]  - mean[c]) / stdv[c];
    osupp[i] = (supp[i] - mean[c]) / stdv[c];
}

// fused: one launch pools both ref and supp pyramids
__global__ void k_avgpool2(const float* __restrict__ inr, const float* __restrict__ ins,
                           float* __restrict__ outr, float* __restrict__ outs,
                           int total, int H, int W) {
    int i = blockIdx.x * blockDim.x + threadIdx.x;
    if (i >= total) return;
    int x = i % W;
    int y = (i / W) % H;
    int nc = i / (W * H);
    size_t so = (size_t)nc * (4 * H * W) + (size_t)(2 * y) * (2 * W) + 2 * x;
    const float* p = inr + so;
    outr[i] = 0.25f * (p[0] + p[1] + p[2 * W] + p[2 * W + 1]);
    p = ins + so;
    outs[i] = 0.25f * (p[0] + p[1] + p[2 * W] + p[2 * W + 1]);
}

// fused: flow upsample + warp + concat; out = fp32 NCHW (out16=0) or compact fp16-split
// 32B/pixel blocks {hi 16B, lo 16B} (out16=1, consumed by conv1-k8)
__global__ void k_prepare2(const float* __restrict__ r, const float* __restrict__ s,
                           const float* __restrict__ flowc, float* __restrict__ fup,
                           void* __restrict__ outv, int H, int W, int lvl0, int out16) {
    int HW = H * W;
    int total = NB * HW;
    int i = blockIdx.x * blockDim.x + threadIdx.x;
    if (i >= total) return;
    int x = i % W;
    int y = (i / W) % H;
    int n = i / HW;
    int pix = y * W + x;

    float f0, f1;
    if (lvl0) {
        f0 = 0.f; f1 = 0.f;
    } else {
        int h = H / 2, w = W / 2;
        float ys = (float)(h - 1) * (float)y / (float)(H - 1);
        float xsf = (float)(w - 1) * (float)x / (float)(W - 1);
        int yy0 = (int)floorf(ys), xx0 = (int)floorf(xsf);
        float wyv = ys - (float)yy0, wxv = xsf - (float)xx0;
        int yy1 = min(yy0 + 1, h - 1), xx1 = min(xx0 + 1, w - 1);
        const float* p0 = flowc + (size_t)(n * 2 + 0) * h * w;
        const float* p1 = p0 + (size_t)h * w;
        {
            float a = p0[yy0 * w + xx0] * (1.f - wyv) + p0[yy1 * w + xx0] * wyv;
            float b = p0[yy0 * w + xx1] * (1.f - wyv) + p0[yy1 * w + xx1] * wyv;
            f0 = 2.0f * (a * (1.f - wxv) + b * wxv);
        }
        {
            float a = p1[yy0 * w + xx0] * (1.f - wyv) + p1[yy1 * w + xx0] * wyv;
            float b = p1[yy0 * w + xx1] * (1.f - wyv) + p1[yy1 * w + xx1] * wyv;
            f1 = 2.0f * (a * (1.f - wxv) + b * wxv);
        }
    }
    fup[((size_t)n * 2 + 0) * HW + pix] = f0;
    fup[((size_t)n * 2 + 1) * HW + pix] = f1;

    float fx = fminf(fmaxf((float)x + f0, 0.f), (float)(W - 1));
    float fy = fminf(fmaxf((float)y + f1, 0.f), (float)(H - 1));
    int x0 = (int)floorf(fx), y0 = (int)floorf(fy);
    int x1 = min(x0 + 1, W - 1), y1 = min(y0 + 1, H - 1);
    float wx = fx - (float)x0, wy = fy - (float)y0;

    float v[8];
#pragma unroll
    for (int c = 0; c < 3; c++) {
        v[c] = r[((size_t)n * 3 + c) * HW + pix];
        const float* sp = s + ((size_t)n * 3 + c) * HW;
        v[3 + c] = sp[y0 * W + x0] * (1.f - wy) * (1.f - wx)
                 + sp[y0 * W + x1] * (1.f - wy) * wx
                 + sp[y1 * W + x0] * wy * (1.f - wx)
                 + sp[y1 * W + x1] * wy * wx;
    }
    v[6] = f0; v[7] = f1;

    if (!out16) {
        float* o = (float*)outv + (size_t)n * 8 * HW + pix;
#pragma unroll
        for (int c = 0; c < 8; c++) o[(size_t)c * HW] = v[c];
    } else {
        uint32_t hw[4], lw[4];
#pragma unroll
        for (int j = 0; j < 4; j++) {
            __half h0, l0, h1, l1;
            split16(v[2 * j], h0, l0);
            split16(v[2 * j + 1], h1, l1);
            hw[j] = pack_h2(h0, h1);
            lw[j] = pack_h2(l0, l1);
        }
        uint4* o = (uint4*)outv + (((size_t)n * H + y) * W + x) * 2;
        o[0] = make_uint4(hw[0], hw[1], hw[2], hw[3]);
        o[1] = make_uint4(lw[0], lw[1], lw[2], lw[3]);
    }
}

// ---------------- weight prep (levels 2-5, convs 2-5 k16 path) ----------------
__global__ void k_wprep_all(const float* __restrict__ w1, const float* __restrict__ w2,
                            const float* __restrict__ w3, const float* __restrict__ w4,
                            const float* __restrict__ w5, uint4* __restrict__ dst) {
    const int LT = 64288;
    int idx = blockIdx.x * blockDim.x + threadIdx.x;
    if (idx >= 4 * LT) return;
    int li = idx / LT;   // 0..3 -> levels 2..5
    int rem = idx % LT;
    const int tot[5]   = {6272, 25088, 25088, 6272, 1568};
    const int cins[5]  = {8, 32, 64, 32, 16};
    const int couts[5] = {32, 64, 32, 16, 2};
    const int NFs[5]   = {4, 8, 4, 2, 1};
    const float* ws[5] = {w1, w2, w3, w4, w5};
    int ci_ = 0;
    while (ci_ < 4 && rem >= tot[ci_]) { rem -= tot[ci_]; ci_++; }
    if (ci_ == 0) { dst[idx] = make_uint4(0, 0, 0, 0); return; }  // conv1 handled by k8 prep
    int Cin = cins[ci_], Cout = couts[ci_], NF = NFs[ci_];
    const float* w = ws[ci_] + (size_t)(2 + li) * Cout * Cin * 49;

    int lane = rem & 31;
    int i2 = rem >> 5;
    int nf = i2 % NF;   i2 /= NF;
    int tap = i2 % 49;
    int chunk = i2 / 49;
    int n = nf * 8 + (lane >> 2);
    int k0 = chunk * 16 + (lane & 3) * 2;
    float v[4];
#pragma unroll
    for (int j = 0; j < 4; j++) {
        int k = k0 + (j >> 1) * 8 + (j & 1);
        v[j] = (n < Cout && k < Cin) ? w[((size_t)n * Cin + k) * 49 + tap] : 0.f;
    }
    __half hh[4], hl[4];
#pragma unroll
    for (int j = 0; j < 4; j++) {
        __half hi = __float2half_rn(v[j]);
        hh[j] = hi;
        hl[j] = __float2half_rn(v[j] - __half2float(hi));
    }
    dst[idx] = make_uint4(pack_h2(hh[0], hh[1]), pack_h2(hh[2], hh[3]),
                          pack_h2(hl[0], hl[1]), pack_h2(hl[2], hl[3]));
}

// conv1 k8 fragments: [li 4][tap 49][nf 4][lane 32] -> uint2 {b0_hi, b0_lo}
__global__ void k_wprep1(const float* __restrict__ w1, uint2* __restrict__ dst) {
    int idx = blockIdx.x * blockDim.x + threadIdx.x;
    if (idx >= 4 * 49 * 4 * 32) return;
    int lane = idx & 31;
    int i2 = idx >> 5;
    int nf = i2 % 4;   i2 /= 4;
    int tap = i2 % 49;
    int li = i2 / 49;
    const float* w = w1 + (size_t)(2 + li) * 32 * 8 * 49;
    int n = nf * 8 + (lane >> 2);
    int k0 = (lane & 3) * 2;
    float v0 = w[((size_t)n * 8 + k0) * 49 + tap];
    float v1 = w[((size_t)n * 8 + k0 + 1) * 49 + tap];
    __half h0, l0, h1, l1;
    split16(v0, h0, l0);
    split16(v1, h1, l1);
    dst[idx] = make_uint2(pack_h2(h0, h1), pack_h2(l0, l1));
}

// ---------------- conv1: k8 mma (Cin=8, Cout=32), levels 2-5 ----------------
__global__ void __launch_bounds__(256, 2)
k_conv1_mma8(const uint4* __restrict__ in, const uint2* __restrict__ bw,
             const float* __restrict__ bias, uint32_t* __restrict__ ob,
             int H, int W) {
    constexpr int MI = 4, NF = 4;
    constexpr int TX = 64, TW = 70;
    constexpr int PART = 14 * TW * 16;   // 15680 bytes per part
    extern __shared__ char smem[];
    uint32_t A0 = smem_u32(smem);

    int tid = threadIdx.x;
    int wid = tid >> 5;
    int lane = tid & 31;

    int x0 = blockIdx.x * TX;
    if (x0 > W - TX) x0 = W - TX;
    if (x0 < 0) x0 = 0;
    int y0 = blockIdx.y * 8;
    int n  = blockIdx.z;

    float C[MI][NF][4];
#pragma unroll
    for (int mi = 0; mi < MI; mi++)
#pragma unroll
        for (int nf = 0; nf < NF; nf++)
#pragma unroll
            for (int j = 0; j < 4; j++) C[mi][nf][j] = 0.f;

    // build: 16B hi + 16B lo per pixel (no swizzle needed: 8 rows = 128B line)
    const uint4* ipc = in + ((size_t)n * H * W) * 2;
    for (int idx = tid; idx < 14 * TW; idx += 256) {
        int r = idx / TW, xt = idx % TW;
        int iy = y0 - 3 + r;
        int ix = x0 - 3 + xt;
        uint4 h = make_uint4(0, 0, 0, 0), l = h;
        if (iy >= 0 && iy < H && ix >= 0 && ix < W) {
            const uint4* sp = ipc + ((size_t)iy * W + ix) * 2;
            h = sp[0]; l = sp[1];
        }
        *(uint4*)(smem + (size_t)idx * 16) = h;
        *(uint4*)(smem + PART + (size_t)idx * 16) = l;
    }
    __syncthreads();

#pragma unroll 1
    for (int tap = 0; tap < 49; tap++) {
        int dy = tap / 7, dx = tap % 7;
        int pixrow = (wid + dy) * TW + dx + (lane & 15);
        uint32_t ah[MI][2], al[MI][2];
#pragma unroll
        for (int mi = 0; mi < MI; mi++) {
            uint32_t at = A0 + (uint32_t)(pixrow + mi * 16) * 16;
            ldmA2(ah[mi], at);
            ldmA2(al[mi], at + PART);
        }
        const uint2* bt = bw + (size_t)tap * NF * 32;
#pragma unroll
        for (int nf = 0; nf < NF; nf++) {
            uint2 wv = bt[nf * 32 + lane];
#pragma unroll
            for (int mi = 0; mi < MI; mi++) {
                mma1688(C[mi][nf], ah[mi], wv.x);
                mma1688(C[mi][nf], ah[mi], wv.y);
                mma1688(C[mi][nf], al[mi], wv.x);
            }
        }
    }

    int y = y0 + wid;
#pragma unroll
    for (int nf = 0; nf < NF; nf++) {
        int c = nf * 8 + (lane & 3) * 2;
        int ch = c >> 4;
        int wd = (c & 15) >> 1;
        float b0 = bias[c], b1 = bias[c + 1];
        size_t rowbase = (((size_t)(n * 2 + ch) * H + y) * W) * 16;
#pragma unroll
        for (int mi = 0; mi < MI; mi++) {
            int xA = x0 + mi * 16 + (lane >> 2);
            float r0 = fmaxf(C[mi][nf][0] + b0, 0.f);
            float r1 = fmaxf(C[mi][nf][1] + b1, 0.f);
            float r2 = fmaxf(C[mi][nf][2] + b0, 0.f);
            float r3 = fmaxf(C[mi][nf][3] + b1, 0.f);
            __half h0, l0, h1, l1, h2, l2, h3, l3;
            split16(r0, h0, l0); split16(r1, h1, l1);
            split16(r2, h2, l2); split16(r3, h3, l3);
            if (xA < W) {
                size_t pb = rowbase + (size_t)xA * 16;
                ob[pb + wd]     = pack_h2(h0, h1);
                ob[pb + 8 + wd] = pack_h2(l0, l1);
            }
            if (xA + 8 < W) {
                size_t pb2 = rowbase + (size_t)(xA + 8) * 16;
                ob[pb2 + wd]     = pack_h2(h2, h3);
                ob[pb2 + 8 + wd] = pack_h2(l2, l3);
            }
        }
    }
}

// ---------------- mma implicit-GEMM 7x7 conv, k16 path (convs 2-5, levels 2-5) ----------------
template <int NF, int MI>
__global__ void __launch_bounds__(256, 2)
k_conv7_mma(const uint4* __restrict__ in, const uint4* __restrict__ bw,
            const float* __restrict__ bias, void* __restrict__ outv,
            const float* __restrict__ resid,
            int nch, int nchO, int Cout, int H, int W, int relu, int out16) {
    constexpr int TX = MI * 16;
    constexpr int TW = TX + 6;
    constexpr int PART = 14 * TW * 32;
    extern __shared__ char smem[];
    uint32_t A0 = smem_u32(smem);

    int tid = threadIdx.x;
    int wid = tid >> 5;
    int lane = tid & 31;

    int x0 = blockIdx.x * TX;
    if (x0 > W - TX) x0 = W - TX;
    if (x0 < 0) x0 = 0;
    int y0 = blockIdx.y * 8;
    int n  = blockIdx.z;

    float C[MI][NF][4];
#pragma unroll
    for (int mi = 0; mi < MI; mi++)
#pragma unroll
        for (int nf = 0; nf < NF; nf++)
#pragma unroll
            for (int j = 0; j < 4; j++) C[mi][nf][j] = 0.f;

    for (int chunk = 0; chunk < nch; chunk++) {
        const uint4* ipc = in + (size_t)(n * nch + chunk) * H * W * 4;
        for (int idx = tid; idx < 14 * TW; idx += 256) {
            int r = idx / TW, xt = idx % TW;
            int iy = y0 - 3 + r;
            int ix = x0 - 3 + xt;
            uint4 h0 = make_uint4(0, 0, 0, 0), h1 = h0, l0 = h0, l1 = h0;
            if (iy >= 0 && iy < H && ix >= 0 && ix < W) {
                const uint4* sp = ipc + ((size_t)iy * W + ix) * 4;
                h0 = sp[0]; h1 = sp[1]; l0 = sp[2]; l1 = sp[3];
            }
            int s = (idx >> 2) & 1;
            uint4* p0 = (uint4*)(smem + (size_t)idx * 32);
            uint4* p1 = (uint4*)(smem + PART + (size_t)idx * 32);
            p0[s]     = h0;
            p0[s ^ 1] = h1;
            p1[s]     = l0;
            p1[s ^ 1] = l1;
        }
        __syncthreads();

        const uint4* bwc = bw + (size_t)chunk * 49 * NF * 32;

#pragma unroll 1
        for (int tap = 0; tap < 49; tap++) {
            int dy = tap / 7, dx = tap % 7;
            int pixrow = (wid + dy) * TW + dx + (lane & 15);
            uint32_t hsel = (((uint32_t)lane >> 4) ^ (((uint32_t)pixrow >> 2) & 1)) << 4;
            uint32_t ah[MI][4], al[MI][4];
#pragma unroll
            for (int mi = 0; mi < MI; mi++) {
                uint32_t at = A0 + (uint32_t)(pixrow + mi * 16) * 32 + hsel;
                ldmA(ah[mi], at);
                ldmA(al[mi], at + PART);
            }
            const uint4* bt = bwc + (size_t)tap * NF * 32;
#pragma unroll
            for (int nf = 0; nf < NF; nf++) {
                uint4 wv = bt[nf * 32 + lane];
#pragma unroll
                for (int mi = 0; mi < MI; mi++) {
                    mma16816(C[mi][nf], ah[mi], wv.x, wv.y);
                    mma16816(C[mi][nf], ah[mi], wv.z, wv.w);
                    mma16816(C[mi][nf], al[mi], wv.x, wv.y);
                }
            }
        }
        if (chunk + 1 < nch) __syncthreads();
    }

    int y = y0 + wid;
    if (out16) {
        uint32_t* ob = (uint32_t*)outv;
#pragma unroll
        for (int nf = 0; nf < NF; nf++) {
            int c = nf * 8 + (lane & 3) * 2;
            int ch = c >> 4;
            int wd = (c & 15) >> 1;
            float b0 = bias[c], b1 = bias[c + 1];
            size_t rowbase = (((size_t)(n * nchO + ch) * H + y) * W) * 16;
#pragma unroll
            for (int mi = 0; mi < MI; mi++) {
                int xA = x0 + mi * 16 + (lane >> 2);
                float r0 = C[mi][nf][0] + b0;
                float r1 = C[mi][nf][1] + b1;
                float r2 = C[mi][nf][2] + b0;
                float r3 = C[mi][nf][3] + b1;
                if (relu) {
                    r0 = fmaxf(r0, 0.f); r1 = fmaxf(r1, 0.f);
                    r2 = fmaxf(r2, 0.f); r3 = fmaxf(r3, 0.f);
                }
                __half h0, l0, h1, l1, h2, l2, h3, l3;
                split16(r0, h0, l0); split16(r1, h1, l1);
                split16(r2, h2, l2); split16(r3, h3, l3);
                if (xA < W) {
                    size_t pb = rowbase + (size_t)xA * 16;
                    ob[pb + wd]     = pack_h2(h0, h1);
                    ob[pb + 8 + wd] = pack_h2(l0, l1);
                }
                if (xA + 8 < W) {
                    size_t pb2 = rowbase + (size_t)(xA + 8) * 16;
                    ob[pb2 + wd]     = pack_h2(h2, h3);
                    ob[pb2 + 8 + wd] = pack_h2(l2, l3);
                }
            }
        }
    } else {
        float* out = (float*)outv;
#pragma unroll
        for (int nf = 0; nf < NF; nf++) {
            int c = nf * 8 + (lane & 3) * 2;
            bool v0 = c < Cout, v1 = c + 1 < Cout;
            float b0 = v0 ? bias[c] : 0.f;
            float b1 = v1 ? bias[c + 1] : 0.f;
            size_t off0 = ((size_t)(n * Cout + c) * H + y) * W;
            float* o0 = out + off0;
            float* o1 = o0 + (size_t)H * W;
            const float* rr0 = resid ? resid + off0 : nullptr;
            const float* rr1 = rr0 + (size_t)H * W;
#pragma unroll
            for (int mi = 0; mi < MI; mi++) {
                int xA = x0 + mi * 16 + (lane >> 2);
                float r0 = C[mi][nf][0] + b0;
                float r1 = C[mi][nf][1] + b1;
                float r2 = C[mi][nf][2] + b0;
                float r3 = C[mi][nf][3] + b1;
                if (relu) {
                    r0 = fmaxf(r0, 0.f); r1 = fmaxf(r1, 0.f);
                    r2 = fmaxf(r2, 0.f); r3 = fmaxf(r3, 0.f);
                }
                if (resid) {
                    if (xA < W) {
                        if (v0) r0 += rr0[xA];
                        if (v1) r1 += rr1[xA];
                    }
                    if (xA + 8 < W) {
                        if (v0) r2 += rr0[xA + 8];
                        if (v1) r3 += rr1[xA + 8];
                    }
                }
                if (xA < W) {
                    if (v0) o0[xA] = r0;
                    if (v1) o1[xA] = r1;
                }
                if (xA + 8 < W) {
                    if (v0) o0[xA + 8] = r2;
                    if (v1) o1[xA + 8] = r3;
                }
            }
        }
    }
}

// ---------------- FFMA f32x2 conv (levels 0-1) ----------------
#define CT 8
__global__ __launch_bounds__(256) void k_conv7(
    const float* __restrict__ in, const float* __restrict__ w,
    const float* __restrict__ bias, float* __restrict__ out,
    const float* __restrict__ resid,
    int Cin, int Cout, int H, int W, int relu) {
    __shared__ __align__(16) float s_in[38 * 40];
    __shared__ __align__(16) float s_w[49][CT];

    int coutGroups = (Cout + CT - 1) / CT;
    int cg = blockIdx.z % coutGroups;
    int n  = blockIdx.z / coutGroups;
    int ox0 = blockIdx.x * 32;
    int oy0 = blockIdx.y * 32;
    int tx = threadIdx.x, ty = threadIdx.y;
    int tid = ty * 16 + tx;

    u64 acc[4][CT / 2];
#pragma unroll
    for (int j = 0; j < CT / 2; j++) {
        int c0 = cg * CT + 2 * j, c1 = c0 + 1;
        float b0 = (c0 < Cout) ? bias[c0] : 0.f;
        float b1 = (c1 < Cout) ? bias[c1] : 0.f;
        u64 b = pack2(b0, b1);
        acc[0][j] = b; acc[1][j] = b; acc[2][j] = b; acc[3][j] = b;
    }

    const float2* s_in2 = (const float2*)s_in;

    for (int ci = 0; ci < Cin; ci++) {
        const float* ip = in + (size_t)(n * Cin + ci) * H * W;
        for (int idx = tid; idx < 38 * 38; idx += 256) {
            int ly = idx / 38, lx = idx % 38;
            int iy = oy0 - 3 + ly, ix = ox0 - 3 + lx;
            s_in[ly * 40 + lx] = (iy >= 0 && iy < H && ix >= 0 && ix < W)
                                     ? ip[(size_t)iy * W + ix] : 0.f;
        }
        for (int idx = tid; idx < CT * 49; idx += 256) {
            int co = idx / 49, k = idx % 49;
            int cout = cg * CT + co;
            s_w[k][co] = (cout < Cout) ? w[((size_t)cout * Cin + ci) * 49 + k] : 0.f;
        }
        __syncthreads();

        float ra[8], rb[8];
        {
            int base2 = ((ty * 2) * 40 + tx * 2) >> 1;
#pragma unroll
            for (int j = 0; j < 4; j++) {
                float2 t = s_in2[base2 + j];
                ra[2 * j] = t.x; ra[2 * j + 1] = t.y;
            }
        }
#pragma unroll
        for (int ky = 0; ky < 7; ky++) {
            int base2 = ((ty * 2 + ky + 1) * 40 + tx * 2) >> 1;
#pragma unroll
            for (int j = 0; j < 4; j++) {
                float2 t = s_in2[base2 + j];
                rb[2 * j] = t.x; rb[2 * j + 1] = t.y;
            }
            u64 da = dup2(ra[0]);
            u64 db = dup2(rb[0]);
#pragma unroll
            for (int kx = 0; kx < 7; kx++) {
                u64 da1 = dup2(ra[kx + 1]);
                u64 db1 = dup2(rb[kx + 1]);
                const u64* wp = (const u64*)&s_w[ky * 7 + kx][0];
#pragma unroll
                for (int j = 0; j < CT / 2; j++) {
                    u64 wv = wp[j];
                    fma2(acc[0][j], da,  wv);
                    fma2(acc[1][j], da1, wv);
                    fma2(acc[2][j], db,  wv);
                    fma2(acc[3][j], db1, wv);
                }
                da = da1; db = db1;
            }
#pragma unroll
            for (int j = 0; j < 8; j++) ra[j] = rb[j];
        }
        __syncthreads();
    }

    int oy = oy0 + ty * 2, ox = ox0 + tx * 2;
#pragma unroll
    for (int j = 0; j < CT / 2; j++) {
        int c0 = cg * CT + 2 * j;
#pragma unroll
        for (int p = 0; p < 4; p++) {
            int yy = oy + (p >> 1), xx = ox + (p & 1);
            if (yy < H && xx < W) {
                float v0, v1;
                unpack2(acc[p][j], v0, v1);
                if (relu) { v0 = fmaxf(v0, 0.f); v1 = fmaxf(v1, 0.f); }
                if (c0 < Cout) {
                    size_t o = (size_t)(n * Cout + c0) * H * W + (size_t)yy * W + xx;
                    out[o] = resid ? (v0 + resid[o]) : v0;
                }
                if (c0 + 1 < Cout) {
                    size_t o = (size_t)(n * Cout + c0 + 1) * H * W + (size_t)yy * W + xx;
                    out[o] = resid ? (v1 + resid[o]) : v1;
                }
            }
        }
    }
}

// ---------------- driver ----------------
extern "C" void kernel_launch(void* const* d_in, const int* in_sizes, int n_in,
                              void* d_out, int out_size) {
    const float* ref  = (const float*)d_in[0];
    const float* supp = (const float*)d_in[1];
    const float* Wt[5] = {(const float*)d_in[2], (const float*)d_in[4],
                          (const float*)d_in[6], (const float*)d_in[8],
                          (const float*)d_in[10]};
    const float* Bt[5] = {(const float*)d_in[3], (const float*)d_in[5],
                          (const float*)d_in[7], (const float*)d_in[9],
                          (const float*)d_in[11]};

    float *pr, *ps, *bufA, *bufB, *flow, *fup;
    uint4* bw;
    uint2* bw1;
    cudaGetSymbolAddress((void**)&pr,   g_pyr_ref);
    cudaGetSymbolAddress((void**)&ps,   g_pyr_supp);
    cudaGetSymbolAddress((void**)&bufA, g_bufA);
    cudaGetSymbolAddress((void**)&bufB, g_bufB);
    cudaGetSymbolAddress((void**)&flow, g_flow);
    cudaGetSymbolAddress((void**)&fup,  g_flowup);
    cudaGetSymbolAddress((void**)&bw,   g_bw);
    cudaGetSymbolAddress((void**)&bw1,  g_bw1);

    const int couts[5]  = {32, 64, 32, 16, 2};
    const int cins[5]   = {8, 32, 64, 32, 16};
    const int nchs[5]   = {1, 2, 4, 2, 1};
    const int nchOs[5]  = {2, 4, 2, 1, 0};
    const int prefix[5] = {0, 6272, 31360, 56448, 62720};
    const int LT = 64288;

    int smem44 = 2 * 14 * (4 * 16 + 6) * 32;  // 62720
    int smem82 = 2 * 14 * (2 * 16 + 6) * 32;  // 34048
    int smemC1 = 2 * 14 * 70 * 16;            // 31360
    cudaFuncSetAttribute(k_conv7_mma<4, 4>, cudaFuncAttributeMaxDynamicSharedMemorySize, smem44);
    cudaFuncSetAttribute(k_conv7_mma<8, 2>, cudaFuncAttributeMaxDynamicSharedMemorySize, smem82);
    cudaFuncSetAttribute(k_conv7_mma<2, 4>, cudaFuncAttributeMaxDynamicSharedMemorySize, smem44);
    cudaFuncSetAttribute(k_conv7_mma<1, 4>, cudaFuncAttributeMaxDynamicSharedMemorySize, smem44);
    cudaFuncSetAttribute(k_conv7_mma<4, 2>, cudaFuncAttributeMaxDynamicSharedMemorySize, smem82);
    cudaFuncSetAttribute(k_conv7_mma<2, 2>, cudaFuncAttributeMaxDynamicSharedMemorySize, smem82);
    cudaFuncSetAttribute(k_conv7_mma<1, 2>, cudaFuncAttributeMaxDynamicSharedMemorySize, smem82);
    cudaFuncSetAttribute(k_conv1_mma8, cudaFuncAttributeMaxDynamicSharedMemorySize, smemC1);

    // ---- weight prep ----
    {
        int total = 4 * LT;
        k_wprep_all<<<(total + 255) / 256, 256>>>(Wt[0], Wt[1], Wt[2], Wt[3], Wt[4], bw);
        int t1 = 4 * 49 * 4 * 32;
        k_wprep1<<<(t1 + 255) / 256, 256>>>(Wt[0], bw1);
    }

    int off[6];
    {
        int o = 0;
        for (int l = 0; l < 6; l++) {
            off[l] = o;
            o += NB * 3 * (8 << l) * (14 << l);
        }
    }

    {
        int HW = 256 * 448;
        int total = NB * 3 * HW;
        k_normalize<<<(total + 255) / 256, 256>>>(ref, supp, pr + off[5], ps + off[5],
                                                  total, HW);
    }
    for (int l = 5; l >= 1; l--) {
        int H = 8 << (l - 1), W = 14 << (l - 1);
        int total = NB * 3 * H * W;
        int g = (total + 255) / 256;
        k_avgpool2<<<g, 256>>>(pr + off[l], ps + off[l], pr + off[l - 1], ps + off[l - 1],
                               total, H, W);
    }

    for (int l = 0; l < 6; l++) {
        int H = 8 << l, W = 14 << l;
        int HW = H * W;

        int tp = NB * HW;
        k_prepare2<<<(tp + 255) / 256, 256>>>(pr + off[l], ps + off[l], flow, fup,
                                              bufA, H, W, (l == 0) ? 1 : 0,
                                              (l >= 2) ? 1 : 0);

        float* dst = (l == 5) ? (float*)d_out : flow;
        float* io[6] = {bufA, bufB, bufA, bufB, bufA, bufB};
        if (l < 2) {
            dim3 blk(16, 16);
            for (int i = 0; i < 5; i++) {
                int Cin = cins[i], Cout = couts[i];
                dim3 grd((W + 31) / 32, (H + 31) / 32, NB * ((Cout + CT - 1) / CT));
                const float* wp = Wt[i] + (size_t)l * Cout * Cin * 49;
                const float* bp = Bt[i] + (size_t)l * Cout;
                float* o = (i == 4) ? dst : io[i + 1];
                const float* rs = (i == 4) ? fup : nullptr;
                k_conv7<<<grd, blk>>>(io[i], wp, bp, o, rs, Cin, Cout, H, W,
                                      (i < 4) ? 1 : 0);
            }
        } else {
            int li = l - 2;
            // levels 2-4 use MI=2 for convs 3-5 (occupancy); level 5 MI=4
            int mi34 = (l == 5) ? 4 : 2;
            for (int i = 0; i < 5; i++) {
                int Cout = couts[i];
                int MI = (i == 1) ? 2 : ((i == 0) ? 4 : mi34);
                int TX = MI * 16;
                int nx = (W + TX - 1) / TX;
                dim3 grd(nx, H / 8, NB);
                const float* bp = Bt[i] + (size_t)l * Cout;
                const uint4* inp = (const uint4*)io[i];
                void* o = (i == 4) ? (void*)dst : (void*)io[i + 1];
                const float* rs = (i == 4) ? fup : nullptr;
                int out16 = (i < 4) ? 1 : 0;
                if (i == 0) {
                    const uint2* bw1p = bw1 + (size_t)li * 49 * 4 * 32;
                    k_conv1_mma8<<<grd, 256, smemC1>>>(inp, bw1p, bp,
                                                       (uint32_t*)io[1], H, W);
                } else {
                    const uint4* bwp = bw + (size_t)li * LT + prefix[i];
                    int sm = (MI == 2) ? smem82 : smem44;
                    if (i == 1)
                        k_conv7_mma<8, 2><<<grd, 256, smem82>>>(inp, bwp, bp, o, rs,
                            nchs[i], nchOs[i], Cout, H, W, 1, out16);
                    else if (i == 2) {
                        if (MI == 2)
                            k_conv7_mma<4, 2><<<grd, 256, sm>>>(inp, bwp, bp, o, rs,
                                nchs[i], nchOs[i], Cout, H, W, 1, out16);
                        else
                            k_conv7_mma<4, 4><<<grd, 256, sm>>>(inp, bwp, bp, o, rs,
                                nchs[i], nchOs[i], Cout, H, W, 1, out16);
                    } else if (i == 3) {
                        if (MI == 2)
                            k_conv7_mma<2, 2><<<grd, 256, sm>>>(inp, bwp, bp, o, rs,
                                nchs[i], nchOs[i], Cout, H, W, 1, out16);
                        else
                            k_conv7_mma<2, 4><<<grd, 256, sm>>>(inp, bwp, bp, o, rs,
                                nchs[i], nchOs[i], Cout, H, W, 1, out16);
                    } else {
                        if (MI == 2)
                            k_conv7_mma<1, 2><<<grd, 256, sm>>>(inp, bwp, bp, o, rs,
                                nchs[i], nchOs[i], Cout, H, W, 0, out16);
                        else
                            k_conv7_mma<1, 4><<<grd, 256, sm>>>(inp, bwp, bp, o, rs,
                                nchs[i], nchOs[i], Cout, H, W, 0, out16);
                    }
                }
            }
        }
    }
    (void)in_sizes; (void)n_in; (void)out_size;
}